// round 4
// baseline (speedup 1.0000x reference)
#include <cuda_runtime.h>
#include <math.h>

#define NC    128
#define LL    250
#define MM    32
#define NCOL  250000
#define TOT   32000000
#define PERB  8000000

// Scratch
__device__ float g_buf0[32000000];  // u -> G (glu out, natural flat) -> u_inter
__device__ float g_buf1[32000000];  // yT -> Lf (lw out, flat)
__device__ float g_buf2[32000000];  // pre-norm
__device__ float g_kern[NC * LL];
__device__ double g_stats[8];

// ---------------------------------------------------------------------------
// f32x2 packed-FMA helpers (sm_100+ PTX)
typedef unsigned long long u64;
__device__ __forceinline__ u64 dup2(float x) {
    u64 r; asm("mov.b64 %0,{%1,%1};" : "=l"(r) : "f"(x)); return r;
}
__device__ __forceinline__ u64 pk2(float x, float y) {
    u64 r; asm("mov.b64 %0,{%1,%2};" : "=l"(r) : "f"(x), "f"(y)); return r;
}
__device__ __forceinline__ void fma2(u64& a, u64 b, u64 c) {
    asm("fma.rn.f32x2 %0,%1,%2,%0;" : "+l"(a) : "l"(b), "l"(c));
}
__device__ __forceinline__ void un2(u64 v, float& x, float& y) {
    asm("mov.b64 {%0,%1},%2;" : "=f"(x), "=f"(y) : "l"(v));
}

// ---------------------------------------------------------------------------
// Pack intra: u[(b*250+s)*128*250 + h*250 + k] = x[((b*128+h)*250 + k)*250 + s]
__global__ void pack_intra(const float* __restrict__ x) {
    __shared__ float tile[32][33];
    int bh = blockIdx.y;            // b*128 + h
    int b = bh >> 7, h = bh & 127;
    int tk = blockIdx.x & 7;
    int ts = blockIdx.x >> 3;
    int k = tk * 32 + threadIdx.y;
    int s = ts * 32 + threadIdx.x;
    if (k < 250 && s < 250)
        tile[threadIdx.y][threadIdx.x] = x[(((long)bh * 250 + k) * 250) + s];
    __syncthreads();
    int s2 = ts * 32 + threadIdx.y;
    int k2 = tk * 32 + threadIdx.x;
    if (s2 < 250 && k2 < 250)
        g_buf0[(((long)(b * 250 + s2) * 128 + h) * 250) + k2] = tile[threadIdx.x][threadIdx.y];
}

// ---------------------------------------------------------------------------
// S4D kernel synthesis
__global__ void kern_compute(const float* __restrict__ log_dt,
                             const float* __restrict__ logA_re,
                             const float* __restrict__ A_im,
                             const float* __restrict__ C_re,
                             const float* __restrict__ C_im) {
    __shared__ float sCr[MM], sCi[MM], sar[MM], sai[MM];
    int h = blockIdx.x;
    int t = threadIdx.x;
    if (t < MM) {
        float dt  = expf(log_dt[h]);
        float Are = -expf(logA_re[h * MM + t]);
        float Aim = A_im[h * MM + t];
        float ar = dt * Are, ai = dt * Aim;
        float ea = expf(ar);
        float sb, cb; sincosf(ai, &sb, &cb);
        float er = ea * cb - 1.f, ei = ea * sb;
        float den = Are * Are + Aim * Aim;
        float qr = (er * Are + ei * Aim) / den;
        float qi = (ei * Are - er * Aim) / den;
        float cr = C_re[h * MM + t], ci = C_im[h * MM + t];
        sCr[t] = cr * qr - ci * qi;
        sCi[t] = cr * qi + ci * qr;
        sar[t] = ar; sai[t] = ai;
    }
    __syncthreads();
    if (t < LL) {
        float fl = (float)t;
        float sum = 0.f;
        #pragma unroll
        for (int m = 0; m < MM; ++m) {
            float ea = expf(sar[m] * fl);
            float sb, cb; sincosf(sai[m] * fl, &sb, &cb);
            sum += ea * (sCr[m] * cb - sCi[m] * sb);
        }
        g_kern[h * LL + t] = 2.f * sum;
    }
}

// ---------------------------------------------------------------------------
// Causal conv + D*u + GELU, v3: conflict-free, row-pair packed f32x2.
// Block: one h, 8 warps; each warp does 2 bb rows packed as float2.
// Lane owns outputs t = lane + 32*i (i=0..7).
__global__ void __launch_bounds__(256) conv_gelu3(const float* __restrict__ D) {
    __shared__ float sk[256];
    __shared__ float2 su2[8][288];    // [warp][32 zero-pad + 250 + 6 pad]
    int tid = threadIdx.x;
    int w = tid >> 5, lane = tid & 31;
    int h = blockIdx.x;
    int pair = blockIdx.y * 8 + w;

    sk[tid] = (tid < 250) ? g_kern[h * 250 + tid] : 0.f;
    __syncthreads();

    if (pair < 500) {
        int bb0 = pair * 2;
        const float* r0 = g_buf0 + ((long)bb0 * 128 + h) * 250;
        const float* r1 = r0 + 128 * 250;
        float2* su = su2[w];
        su[lane] = make_float2(0.f, 0.f);
        if (lane < 6) su[282 + lane] = make_float2(0.f, 0.f);
        for (int t = lane; t < 250; t += 32)
            su[32 + t] = make_float2(r0[t], r1[t]);
        __syncwarp();

        u64 acc[8];
        #pragma unroll
        for (int i = 0; i < 8; ++i) acc[i] = 0ull;

        for (int jb = 0; jb < 256; jb += 8) {
            float4 k0 = *(const float4*)&sk[jb];
            float4 k1 = *(const float4*)&sk[jb + 4];
            u64 kd[8] = {dup2(k0.x), dup2(k0.y), dup2(k0.z), dup2(k0.w),
                         dup2(k1.x), dup2(k1.y), dup2(k1.z), dup2(k1.w)};
            #pragma unroll
            for (int i = 0; i < 8; ++i) {
                if (32 * i + 32 > jb) {   // triangular prune (warp-uniform)
                    int m = 32 + lane + 32 * i - jb;
                    #pragma unroll
                    for (int e = 0; e < 8; ++e) {
                        u64 uv = *(const u64*)&su[m - e];
                        fma2(acc[i], kd[e], uv);
                    }
                }
            }
        }
        __syncwarp();

        float dh = D[h];
        long ob0 = (long)h * NCOL + (long)bb0 * 250;
        #pragma unroll
        for (int i = 0; i < 8; ++i) {
            int t = lane + 32 * i;
            float y0, y1; un2(acc[i], y0, y1);
            float2 uv = su[32 + t];
            y0 += dh * uv.x; y1 += dh * uv.y;
            float c0 = y0 + 0.044715f * y0 * y0 * y0;
            float c1 = y1 + 0.044715f * y1 * y1 * y1;
            float g0 = 0.5f * y0 * (1.f + tanhf(0.7978845608f * c0));
            float g1 = 0.5f * y1 * (1.f + tanhf(0.7978845608f * c1));
            if (t < 250) {
                g_buf1[ob0 + t] = g0;
                g_buf1[ob0 + 250 + t] = g1;
            }
        }
    }
}

// ---------------------------------------------------------------------------
// Fused ow GEMM + GLU (two row-phases; phase 0 stashed in smem).
#define PITCH 132
__global__ void __launch_bounds__(256, 2)
gemm_ow_glu(const float* __restrict__ A, const float* __restrict__ bias) {
    extern __shared__ float sm[];
    float* As = sm;                    // [32][PITCH]
    float* Bs = sm + 32 * PITCH;       // [32][PITCH]
    float* Zs = sm + 64 * PITCH;       // [128][PITCH]
    const float* __restrict__ Bm = g_buf1;

    int tid = threadIdx.x;
    int tx = tid & 15, ty = tid >> 4;
    long n0 = (long)blockIdx.x * 128;

    for (int phase = 0; phase < 2; ++phase) {
        int m0 = phase * 128;
        u64 acc[8][4];
        #pragma unroll
        for (int i = 0; i < 8; ++i)
            #pragma unroll
            for (int j = 0; j < 4; ++j) acc[i][j] = 0ull;

        for (int kc = 0; kc < 4; ++kc) {
            {
                int c4 = (tid & 7) * 4;
                int rb = tid >> 3;
                #pragma unroll
                for (int p = 0; p < 4; ++p) {
                    int r = rb + p * 32;
                    float4 v = *(const float4*)(A + (long)(m0 + r) * 128 + kc * 32 + c4);
                    As[(c4 + 0) * PITCH + r] = v.x; As[(c4 + 1) * PITCH + r] = v.y;
                    As[(c4 + 2) * PITCH + r] = v.z; As[(c4 + 3) * PITCH + r] = v.w;
                }
            }
            {
                int n4 = (tid & 31) * 4;
                int kb = tid >> 5;
                #pragma unroll
                for (int p = 0; p < 4; ++p) {
                    int kr = kb + p * 8;
                    long col = n0 + n4;
                    const float* bp = Bm + (long)(kc * 32 + kr) * NCOL + col;
                    float4 v;
                    if (col + 4 <= NCOL) v = *(const float4*)bp;
                    else {
                        v.x = (col + 0 < NCOL) ? bp[0] : 0.f;
                        v.y = (col + 1 < NCOL) ? bp[1] : 0.f;
                        v.z = (col + 2 < NCOL) ? bp[2] : 0.f;
                        v.w = (col + 3 < NCOL) ? bp[3] : 0.f;
                    }
                    *(float4*)&Bs[kr * PITCH + n4] = v;
                }
            }
            __syncthreads();
            #pragma unroll
            for (int kk = 0; kk < 32; ++kk) {
                float4 a0 = *(const float4*)&As[kk * PITCH + ty * 8];
                float4 a1 = *(const float4*)&As[kk * PITCH + ty * 8 + 4];
                ulonglong2 bq0 = *(const ulonglong2*)&Bs[kk * PITCH + tx * 8];
                ulonglong2 bq1 = *(const ulonglong2*)&Bs[kk * PITCH + tx * 8 + 4];
                u64 ad[8] = {dup2(a0.x), dup2(a0.y), dup2(a0.z), dup2(a0.w),
                             dup2(a1.x), dup2(a1.y), dup2(a1.z), dup2(a1.w)};
                u64 bp4[4] = {bq0.x, bq0.y, bq1.x, bq1.y};
                #pragma unroll
                for (int i = 0; i < 8; ++i)
                    #pragma unroll
                    for (int j = 0; j < 4; ++j)
                        fma2(acc[i][j], ad[i], bp4[j]);
            }
            __syncthreads();
        }

        if (phase == 0) {
            #pragma unroll
            for (int i = 0; i < 8; ++i) {
                int row = ty * 8 + i;
                float bv = bias[row];
                float c[8];
                #pragma unroll
                for (int j = 0; j < 4; ++j) un2(acc[i][j], c[2 * j], c[2 * j + 1]);
                float4 v0 = {c[0] + bv, c[1] + bv, c[2] + bv, c[3] + bv};
                float4 v1 = {c[4] + bv, c[5] + bv, c[6] + bv, c[7] + bv};
                *(float4*)&Zs[row * PITCH + tx * 8]     = v0;
                *(float4*)&Zs[row * PITCH + tx * 8 + 4] = v1;
            }
        } else {
            #pragma unroll
            for (int i = 0; i < 8; ++i) {
                int o = ty * 8 + i;
                float bv = bias[128 + o];
                float c[8];
                #pragma unroll
                for (int j = 0; j < 4; ++j) un2(acc[i][j], c[2 * j], c[2 * j + 1]);
                #pragma unroll
                for (int j = 0; j < 8; ++j) {
                    long col = n0 + tx * 8 + j;
                    if (col < NCOL) {
                        float z1 = Zs[o * PITCH + tx * 8 + j];
                        float z2 = c[j] + bv;
                        float g = z1 / (1.f + expf(-z2));
                        int bb = (int)(col / 250);
                        int l  = (int)(col - (long)bb * 250);
                        g_buf0[((long)bb * 128 + o) * 250 + l] = g;
                    }
                }
            }
        }
        __syncthreads();
    }
}

// ---------------------------------------------------------------------------
// GEMM2 (lw) on flat rows: C[r][c] = sum_k G[r][k] * W[c][k] + lb[c]
__global__ void __launch_bounds__(256, 2)
gemm_lw(const float* __restrict__ W, const float* __restrict__ bias) {
    const float* __restrict__ G = g_buf0;
    float* __restrict__ C = g_buf1;
    __shared__ float Gs[32 * PITCH];
    __shared__ float Ws[32 * PITCH];

    int tid = threadIdx.x;
    int tx = tid & 15, ty = tid >> 4;
    long r0 = (long)blockIdx.x * 128;

    u64 acc[8][4];
    #pragma unroll
    for (int i = 0; i < 8; ++i)
        #pragma unroll
        for (int j = 0; j < 4; ++j) acc[i][j] = 0ull;

    for (int kc = 0; kc < 4; ++kc) {
        int c4 = (tid & 7) * 4;
        int rb = tid >> 3;
        #pragma unroll
        for (int p = 0; p < 4; ++p) {
            int r = rb + p * 32;
            long grow = r0 + r;
            if (grow >= NCOL) grow = NCOL - 1;
            float4 v = *(const float4*)(G + grow * 128 + kc * 32 + c4);
            Gs[(c4 + 0) * PITCH + r] = v.x; Gs[(c4 + 1) * PITCH + r] = v.y;
            Gs[(c4 + 2) * PITCH + r] = v.z; Gs[(c4 + 3) * PITCH + r] = v.w;
            float4 wv = *(const float4*)(W + (long)r * 128 + kc * 32 + c4);
            Ws[(c4 + 0) * PITCH + r] = wv.x; Ws[(c4 + 1) * PITCH + r] = wv.y;
            Ws[(c4 + 2) * PITCH + r] = wv.z; Ws[(c4 + 3) * PITCH + r] = wv.w;
        }
        __syncthreads();
        #pragma unroll
        for (int kk = 0; kk < 32; ++kk) {
            float4 a0 = *(const float4*)&Gs[kk * PITCH + ty * 8];
            float4 a1 = *(const float4*)&Gs[kk * PITCH + ty * 8 + 4];
            ulonglong2 bq0 = *(const ulonglong2*)&Ws[kk * PITCH + tx * 8];
            ulonglong2 bq1 = *(const ulonglong2*)&Ws[kk * PITCH + tx * 8 + 4];
            u64 ad[8] = {dup2(a0.x), dup2(a0.y), dup2(a0.z), dup2(a0.w),
                         dup2(a1.x), dup2(a1.y), dup2(a1.z), dup2(a1.w)};
            u64 bp4[4] = {bq0.x, bq0.y, bq1.x, bq1.y};
            #pragma unroll
            for (int i = 0; i < 8; ++i)
                #pragma unroll
                for (int j = 0; j < 4; ++j)
                    fma2(acc[i][j], ad[i], bp4[j]);
        }
        __syncthreads();
    }
    float bb0[8];
    {
        float4 b0 = *(const float4*)(bias + tx * 8);
        float4 b1 = *(const float4*)(bias + tx * 8 + 4);
        bb0[0] = b0.x; bb0[1] = b0.y; bb0[2] = b0.z; bb0[3] = b0.w;
        bb0[4] = b1.x; bb0[5] = b1.y; bb0[6] = b1.z; bb0[7] = b1.w;
    }
    #pragma unroll
    for (int i = 0; i < 8; ++i) {
        long row = r0 + ty * 8 + i;
        if (row >= NCOL) continue;
        float c[8];
        #pragma unroll
        for (int j = 0; j < 4; ++j) un2(acc[i][j], c[2 * j], c[2 * j + 1]);
        float4 v0 = {c[0] + bb0[0], c[1] + bb0[1], c[2] + bb0[2], c[3] + bb0[3]};
        float4 v1 = {c[4] + bb0[4], c[5] + bb0[5], c[6] + bb0[6], c[7] + bb0[7]};
        float* cp = C + row * 128 + tx * 8;
        *(float4*)(cp) = v0;
        *(float4*)(cp + 4) = v1;
    }
}

// ---------------------------------------------------------------------------
__global__ void zero_stats() {
    if (threadIdx.x < 8) g_stats[threadIdx.x] = 0.0;
}

// intra: pre[b][n][k][s] = Lf[(b*250+s)*32000 + n*250 + k]; tiled transpose + stats
__global__ void trans_stats_intra() {
    __shared__ float tile[32][33];
    __shared__ float rs[32], rq[32];
    int bn = blockIdx.y;
    int b = bn >> 7, n = bn & 127;
    int tk = blockIdx.x & 7, ts = blockIdx.x >> 3;
    int s = ts * 32 + threadIdx.y;
    int k = tk * 32 + threadIdx.x;
    float v = 0.f;
    if (s < 250 && k < 250)
        v = g_buf1[((long)(b * 250 + s)) * 32000 + n * 250 + k];
    tile[threadIdx.y][threadIdx.x] = v;
    __syncthreads();
    int k2 = tk * 32 + threadIdx.y;
    int s2 = ts * 32 + threadIdx.x;
    float wv = tile[threadIdx.x][threadIdx.y];
    bool ok = (k2 < 250 && s2 < 250);
    if (ok)
        g_buf2[(((long)bn * 250 + k2) * 250) + s2] = wv;
    float sum = ok ? wv : 0.f;
    float sq = sum * sum;
    #pragma unroll
    for (int off = 16; off; off >>= 1) {
        sum += __shfl_down_sync(0xffffffffu, sum, off);
        sq  += __shfl_down_sync(0xffffffffu, sq, off);
    }
    if (threadIdx.x == 0) { rs[threadIdx.y] = sum; rq[threadIdx.y] = sq; }
    __syncthreads();
    if (threadIdx.y == 0) {
        float a = rs[threadIdx.x], q = rq[threadIdx.x];
        #pragma unroll
        for (int off = 16; off; off >>= 1) {
            a += __shfl_down_sync(0xffffffffu, a, off);
            q += __shfl_down_sync(0xffffffffu, q, off);
        }
        if (threadIdx.x == 0) {
            atomicAdd(&g_stats[2 * b], (double)a);
            atomicAdd(&g_stats[2 * b + 1], (double)q);
        }
    }
}

// inter: pre[b][n][k][s] = Lf[(b*250+k)*32000 + n*250 + s]; coalesced copy + stats
__global__ void copy_stats_inter() {
    int i = blockIdx.x * 256 + threadIdx.x;
    int s = i % 250;
    int t = i / 250;
    int k = t % 250; t /= 250;
    int n = t & 127;
    int b = t >> 7;
    float v = g_buf1[((long)(b * 250 + k)) * 32000 + n * 250 + s];
    g_buf2[i] = v;
    float sum = v, sq = v * v;
    #pragma unroll
    for (int off = 16; off; off >>= 1) {
        sum += __shfl_down_sync(0xffffffffu, sum, off);
        sq  += __shfl_down_sync(0xffffffffu, sq, off);
    }
    __shared__ float ssum[8], ssq[8];
    int lane = threadIdx.x & 31, w = threadIdx.x >> 5;
    if (lane == 0) { ssum[w] = sum; ssq[w] = sq; }
    __syncthreads();
    if (threadIdx.x == 0) {
        float a = 0.f, q = 0.f;
        #pragma unroll
        for (int j = 0; j < 8; ++j) { a += ssum[j]; q += ssq[j]; }
        atomicAdd(&g_stats[2 * b], (double)a);
        atomicAdd(&g_stats[2 * b + 1], (double)q);
    }
}

// GroupNorm apply + residual; intra version also emits inter-path u (fused pack)
__global__ void norm_intra(const float* __restrict__ gg, const float* __restrict__ gb,
                           const float* __restrict__ x, float* __restrict__ out) {
    int i = blockIdx.x * 256 + threadIdx.x;
    int s = i % 250;
    int t = i / 250;
    int k = t % 250; t /= 250;
    int n = t & 127;
    int b = t >> 7;
    double mu  = g_stats[2 * b] / (double)PERB;
    double var = g_stats[2 * b + 1] / (double)PERB - mu * mu;
    float inv = (float)(1.0 / sqrt(var + 1e-8));
    float val = (g_buf2[i] - (float)mu) * inv * gg[n] + gb[n] + x[i];
    out[i] = val;
    g_buf0[(((long)(b * 250 + k)) * 128 + n) * 250 + s] = val;
}

__global__ void norm_final(const float* __restrict__ gg, const float* __restrict__ gb,
                           float* __restrict__ out) {
    int i = blockIdx.x * 256 + threadIdx.x;
    int n = (i / 62500) & 127;
    int b = i / PERB;
    double mu  = g_stats[2 * b] / (double)PERB;
    double var = g_stats[2 * b + 1] / (double)PERB - mu * mu;
    float inv = (float)(1.0 / sqrt(var + 1e-8));
    out[i] = (g_buf2[i] - (float)mu) * inv * gg[n] + gb[n] + out[i];
}

// ---------------------------------------------------------------------------
extern "C" void kernel_launch(void* const* d_in, const int* in_sizes, int n_in,
                              void* d_out, int out_size) {
    const float* x = (const float*)d_in[0];
    const float* ip[12];
    const float* pp[12];
    for (int j = 0; j < 12; ++j) ip[j] = (const float*)d_in[1 + j];
    for (int j = 0; j < 12; ++j) pp[j] = (const float*)d_in[13 + j];
    float* out = (float*)d_out;

    const int EB = TOT / 256;
    const int SMEM_OWGLU = (64 * PITCH + 128 * PITCH) * sizeof(float);  // ~99KB
    cudaFuncSetAttribute(gemm_ow_glu, cudaFuncAttributeMaxDynamicSharedMemorySize, SMEM_OWGLU);

    // ---- intra path ----
    pack_intra<<<dim3(64, 512), dim3(32, 32)>>>(x);
    kern_compute<<<NC, 256>>>(ip[0], ip[1], ip[2], ip[3], ip[4]);
    conv_gelu3<<<dim3(128, 63), 256>>>(ip[5]);
    gemm_ow_glu<<<1954, 256, SMEM_OWGLU>>>(ip[6], ip[7]);
    gemm_lw<<<1954, 256>>>(ip[8], ip[9]);
    zero_stats<<<1, 32>>>();
    trans_stats_intra<<<dim3(64, 512), dim3(32, 32)>>>();
    norm_intra<<<EB, 256>>>(ip[10], ip[11], x, out);

    // ---- inter path ----
    kern_compute<<<NC, 256>>>(pp[0], pp[1], pp[2], pp[3], pp[4]);
    conv_gelu3<<<dim3(128, 63), 256>>>(pp[5]);
    gemm_ow_glu<<<1954, 256, SMEM_OWGLU>>>(pp[6], pp[7]);
    gemm_lw<<<1954, 256>>>(pp[8], pp[9]);
    zero_stats<<<1, 32>>>();
    copy_stats_inter<<<EB, 256>>>();
    norm_final<<<EB, 256>>>(pp[10], pp[11], out);
}

// round 5
// speedup vs baseline: 1.1014x; 1.1014x over previous
#include <cuda_runtime.h>
#include <math.h>

#define NC    128
#define LL    250
#define MM    32
#define NCOL  250000
#define TOT   32000000
#define PERB  8000000
#define PITCH 132

// Scratch
__device__ float g_buf0[32000000];  // u -> G (glu out, natural flat) -> u_inter
__device__ float g_buf1[32000000];  // yT -> Lf (lw out, flat)
__device__ float g_buf2[32000000];  // pre-norm
__device__ float g_kern[NC * LL];
__device__ double g_stats[8];

// ---------------------------------------------------------------------------
// f32x2 packed-FMA helpers (sm_100+ PTX)
typedef unsigned long long u64;
__device__ __forceinline__ u64 dup2(float x) {
    u64 r; asm("mov.b64 %0,{%1,%1};" : "=l"(r) : "f"(x)); return r;
}
__device__ __forceinline__ u64 pk2(float x, float y) {
    u64 r; asm("mov.b64 %0,{%1,%2};" : "=l"(r) : "f"(x), "f"(y)); return r;
}
__device__ __forceinline__ void fma2(u64& a, u64 b, u64 c) {
    asm("fma.rn.f32x2 %0,%1,%2,%0;" : "+l"(a) : "l"(b), "l"(c));
}
__device__ __forceinline__ void un2(u64 v, float& x, float& y) {
    asm("mov.b64 {%0,%1},%2;" : "=f"(x), "=f"(y) : "l"(v));
}

// ---------------------------------------------------------------------------
// Pack intra: u[(b*250+s)*128*250 + h*250 + k] = x[((b*128+h)*250 + k)*250 + s]
__global__ void pack_intra(const float* __restrict__ x) {
    __shared__ float tile[32][33];
    int bh = blockIdx.y;            // b*128 + h
    int b = bh >> 7, h = bh & 127;
    int tk = blockIdx.x & 7;
    int ts = blockIdx.x >> 3;
    int k = tk * 32 + threadIdx.y;
    int s = ts * 32 + threadIdx.x;
    if (k < 250 && s < 250)
        tile[threadIdx.y][threadIdx.x] = x[(((long)bh * 250 + k) * 250) + s];
    __syncthreads();
    int s2 = ts * 32 + threadIdx.y;
    int k2 = tk * 32 + threadIdx.x;
    if (s2 < 250 && k2 < 250)
        g_buf0[(((long)(b * 250 + s2) * 128 + h) * 250) + k2] = tile[threadIdx.x][threadIdx.y];
}

// ---------------------------------------------------------------------------
// S4D kernel synthesis
__global__ void kern_compute(const float* __restrict__ log_dt,
                             const float* __restrict__ logA_re,
                             const float* __restrict__ A_im,
                             const float* __restrict__ C_re,
                             const float* __restrict__ C_im) {
    __shared__ float sCr[MM], sCi[MM], sar[MM], sai[MM];
    int h = blockIdx.x;
    int t = threadIdx.x;
    if (t < MM) {
        float dt  = expf(log_dt[h]);
        float Are = -expf(logA_re[h * MM + t]);
        float Aim = A_im[h * MM + t];
        float ar = dt * Are, ai = dt * Aim;
        float ea = expf(ar);
        float sb, cb; sincosf(ai, &sb, &cb);
        float er = ea * cb - 1.f, ei = ea * sb;
        float den = Are * Are + Aim * Aim;
        float qr = (er * Are + ei * Aim) / den;
        float qi = (ei * Are - er * Aim) / den;
        float cr = C_re[h * MM + t], ci = C_im[h * MM + t];
        sCr[t] = cr * qr - ci * qi;
        sCi[t] = cr * qi + ci * qr;
        sar[t] = ar; sai[t] = ai;
    }
    __syncthreads();
    if (t < LL) {
        float fl = (float)t;
        float sum = 0.f;
        #pragma unroll
        for (int m = 0; m < MM; ++m) {
            float ea = expf(sar[m] * fl);
            float sb, cb; sincosf(sai[m] * fl, &sb, &cb);
            sum += ea * (sCr[m] * cb - sCi[m] * sb);
        }
        g_kern[h * LL + t] = 2.f * sum;
    }
}

// ---------------------------------------------------------------------------
// Conv as per-h Toeplitz GEMM + D*u + GELU.
// For each h: Y[bb][t] = sum_m U[bb][m] * k_h[t-m]   (k out-of-range -> 0)
// Tiles: 128 bb-rows x 128 t-cols; k-depth = 128 (colblk 0) or 256 (colblk 1).
// Epilogue: y = Y + D[h]*u; gelu; write yT[h][bb*250 + t] (gemm_ow B layout).
__global__ void __launch_bounds__(256, 2)
conv_gemm(const float* __restrict__ D) {
    __shared__ float As[32 * PITCH];   // [m][bb]
    __shared__ float Bs[32 * PITCH];   // [m][t]
    __shared__ float skp[512];         // 256 zeros | k[0..249] | zeros
    int tid = threadIdx.x;
    int h = blockIdx.y;
    int rowblk = blockIdx.x >> 1, colblk = blockIdx.x & 1;
    int r0 = rowblk * 128;             // bb base (0..896)
    int t0 = colblk * 128;
    int nkt = colblk ? 8 : 4;

    skp[tid] = 0.f;
    skp[256 + tid] = (tid < 250) ? g_kern[h * 250 + tid] : 0.f;
    __syncthreads();

    int tx = tid & 15, ty = tid >> 4;
    u64 acc[8][4];
    #pragma unroll
    for (int i = 0; i < 8; ++i)
        #pragma unroll
        for (int j = 0; j < 4; ++j) acc[i][j] = 0ull;

    for (int kt = 0; kt < nkt; ++kt) {
        int m0 = kt * 32;
        // A tile (transposed store): As[mm][r] = U[r0+r][m0+mm]
        {
            int c4 = (tid & 7) * 4;    // mm base
            int rb = tid >> 3;
            #pragma unroll
            for (int p = 0; p < 4; ++p) {
                int r = rb + p * 32;
                int bb = r0 + r; if (bb > 999) bb = 999;
                const float* up = g_buf0 + ((long)bb * 128 + h) * 250 + m0 + c4;
                // float2 loads (8B alignment always holds); zero beyond m=249
                float2 v0 = (m0 + c4     < 250) ? *(const float2*)(up)     : make_float2(0.f, 0.f);
                float2 v1 = (m0 + c4 + 2 < 250) ? *(const float2*)(up + 2) : make_float2(0.f, 0.f);
                As[(c4 + 0) * PITCH + r] = v0.x; As[(c4 + 1) * PITCH + r] = v0.y;
                As[(c4 + 2) * PITCH + r] = v1.x; As[(c4 + 3) * PITCH + r] = v1.y;
            }
        }
        // B tile (Toeplitz): Bs[mm][tt] = skp[256 + t0 - m0 - mm + tt]
        {
            int mm = tid >> 3;
            int ttb = (tid & 7) * 16;
            int base = 256 + t0 - m0 - mm + ttb;
            #pragma unroll
            for (int q = 0; q < 16; ++q)
                Bs[mm * PITCH + ttb + q] = skp[base + q];
        }
        __syncthreads();
        #pragma unroll
        for (int kk = 0; kk < 32; ++kk) {
            float4 a0 = *(const float4*)&As[kk * PITCH + ty * 8];
            float4 a1 = *(const float4*)&As[kk * PITCH + ty * 8 + 4];
            float4 b0 = *(const float4*)&Bs[kk * PITCH + tx * 8];
            float4 b1 = *(const float4*)&Bs[kk * PITCH + tx * 8 + 4];
            u64 ad[8] = {dup2(a0.x), dup2(a0.y), dup2(a0.z), dup2(a0.w),
                         dup2(a1.x), dup2(a1.y), dup2(a1.z), dup2(a1.w)};
            u64 bp4[4] = {pk2(b0.x, b0.y), pk2(b0.z, b0.w),
                          pk2(b1.x, b1.y), pk2(b1.z, b1.w)};
            #pragma unroll
            for (int i = 0; i < 8; ++i)
                #pragma unroll
                for (int j = 0; j < 4; ++j)
                    fma2(acc[i][j], ad[i], bp4[j]);
        }
        __syncthreads();
    }

    // Epilogue: + D*u, gelu, store yT[h][bb*250 + t]  (float2: 8B-aligned)
    float dh = D[h];
    #pragma unroll
    for (int i = 0; i < 8; ++i) {
        int bb = r0 + ty * 8 + i;
        if (bb > 999) continue;
        float c[8];
        #pragma unroll
        for (int j = 0; j < 4; ++j) un2(acc[i][j], c[2 * j], c[2 * j + 1]);
        int tbase = t0 + tx * 8;
        const float* up = g_buf0 + ((long)bb * 128 + h) * 250 + tbase;
        float* yp = g_buf1 + (long)h * NCOL + (long)bb * 250 + tbase;
        #pragma unroll
        for (int j2 = 0; j2 < 4; ++j2) {
            int t = tbase + 2 * j2;
            if (t < 250) {
                float2 uv = *(const float2*)(up + 2 * j2);
                float y0 = c[2 * j2]     + dh * uv.x;
                float y1 = c[2 * j2 + 1] + dh * uv.y;
                float e0 = y0 + 0.044715f * y0 * y0 * y0;
                float e1 = y1 + 0.044715f * y1 * y1 * y1;
                float2 g;
                g.x = 0.5f * y0 * (1.f + tanhf(0.7978845608f * e0));
                g.y = 0.5f * y1 * (1.f + tanhf(0.7978845608f * e1));
                *(float2*)(yp + 2 * j2) = g;
            }
        }
    }
}

// ---------------------------------------------------------------------------
// Fused ow GEMM + GLU (two row-phases; phase 0 stashed in smem).
__global__ void __launch_bounds__(256, 2)
gemm_ow_glu(const float* __restrict__ A, const float* __restrict__ bias) {
    extern __shared__ float sm[];
    float* As = sm;                    // [32][PITCH]
    float* Bs = sm + 32 * PITCH;       // [32][PITCH]
    float* Zs = sm + 64 * PITCH;       // [128][PITCH]
    const float* __restrict__ Bm = g_buf1;

    int tid = threadIdx.x;
    int tx = tid & 15, ty = tid >> 4;
    long n0 = (long)blockIdx.x * 128;

    for (int phase = 0; phase < 2; ++phase) {
        int m0 = phase * 128;
        u64 acc[8][4];
        #pragma unroll
        for (int i = 0; i < 8; ++i)
            #pragma unroll
            for (int j = 0; j < 4; ++j) acc[i][j] = 0ull;

        for (int kc = 0; kc < 4; ++kc) {
            {
                int c4 = (tid & 7) * 4;
                int rb = tid >> 3;
                #pragma unroll
                for (int p = 0; p < 4; ++p) {
                    int r = rb + p * 32;
                    float4 v = *(const float4*)(A + (long)(m0 + r) * 128 + kc * 32 + c4);
                    As[(c4 + 0) * PITCH + r] = v.x; As[(c4 + 1) * PITCH + r] = v.y;
                    As[(c4 + 2) * PITCH + r] = v.z; As[(c4 + 3) * PITCH + r] = v.w;
                }
            }
            {
                int n4 = (tid & 31) * 4;
                int kb = tid >> 5;
                #pragma unroll
                for (int p = 0; p < 4; ++p) {
                    int kr = kb + p * 8;
                    long col = n0 + n4;
                    const float* bp = Bm + (long)(kc * 32 + kr) * NCOL + col;
                    float4 v;
                    if (col + 4 <= NCOL) v = *(const float4*)bp;
                    else {
                        v.x = (col + 0 < NCOL) ? bp[0] : 0.f;
                        v.y = (col + 1 < NCOL) ? bp[1] : 0.f;
                        v.z = (col + 2 < NCOL) ? bp[2] : 0.f;
                        v.w = (col + 3 < NCOL) ? bp[3] : 0.f;
                    }
                    *(float4*)&Bs[kr * PITCH + n4] = v;
                }
            }
            __syncthreads();
            #pragma unroll
            for (int kk = 0; kk < 32; ++kk) {
                float4 a0 = *(const float4*)&As[kk * PITCH + ty * 8];
                float4 a1 = *(const float4*)&As[kk * PITCH + ty * 8 + 4];
                float4 b0 = *(const float4*)&Bs[kk * PITCH + tx * 8];
                float4 b1 = *(const float4*)&Bs[kk * PITCH + tx * 8 + 4];
                u64 ad[8] = {dup2(a0.x), dup2(a0.y), dup2(a0.z), dup2(a0.w),
                             dup2(a1.x), dup2(a1.y), dup2(a1.z), dup2(a1.w)};
                u64 bp4[4] = {pk2(b0.x, b0.y), pk2(b0.z, b0.w),
                              pk2(b1.x, b1.y), pk2(b1.z, b1.w)};
                #pragma unroll
                for (int i = 0; i < 8; ++i)
                    #pragma unroll
                    for (int j = 0; j < 4; ++j)
                        fma2(acc[i][j], ad[i], bp4[j]);
            }
            __syncthreads();
        }

        if (phase == 0) {
            #pragma unroll
            for (int i = 0; i < 8; ++i) {
                int row = ty * 8 + i;
                float bv = bias[row];
                float c[8];
                #pragma unroll
                for (int j = 0; j < 4; ++j) un2(acc[i][j], c[2 * j], c[2 * j + 1]);
                float4 v0 = {c[0] + bv, c[1] + bv, c[2] + bv, c[3] + bv};
                float4 v1 = {c[4] + bv, c[5] + bv, c[6] + bv, c[7] + bv};
                *(float4*)&Zs[row * PITCH + tx * 8]     = v0;
                *(float4*)&Zs[row * PITCH + tx * 8 + 4] = v1;
            }
        } else {
            #pragma unroll
            for (int i = 0; i < 8; ++i) {
                int o = ty * 8 + i;
                float bv = bias[128 + o];
                float c[8];
                #pragma unroll
                for (int j = 0; j < 4; ++j) un2(acc[i][j], c[2 * j], c[2 * j + 1]);
                #pragma unroll
                for (int j = 0; j < 8; ++j) {
                    long col = n0 + tx * 8 + j;
                    if (col < NCOL) {
                        float z1 = Zs[o * PITCH + tx * 8 + j];
                        float z2 = c[j] + bv;
                        float g = z1 / (1.f + expf(-z2));
                        int bb = (int)(col / 250);
                        int l  = (int)(col - (long)bb * 250);
                        g_buf0[((long)bb * 128 + o) * 250 + l] = g;
                    }
                }
            }
        }
        __syncthreads();
    }
}

// ---------------------------------------------------------------------------
// GEMM2 (lw) on flat rows: C[r][c] = sum_k G[r][k] * W[c][k] + lb[c]
__global__ void __launch_bounds__(256, 2)
gemm_lw(const float* __restrict__ W, const float* __restrict__ bias) {
    const float* __restrict__ G = g_buf0;
    float* __restrict__ C = g_buf1;
    __shared__ float Gs[32 * PITCH];
    __shared__ float Ws[32 * PITCH];

    int tid = threadIdx.x;
    int tx = tid & 15, ty = tid >> 4;
    long r0 = (long)blockIdx.x * 128;

    u64 acc[8][4];
    #pragma unroll
    for (int i = 0; i < 8; ++i)
        #pragma unroll
        for (int j = 0; j < 4; ++j) acc[i][j] = 0ull;

    for (int kc = 0; kc < 4; ++kc) {
        int c4 = (tid & 7) * 4;
        int rb = tid >> 3;
        #pragma unroll
        for (int p = 0; p < 4; ++p) {
            int r = rb + p * 32;
            long grow = r0 + r;
            if (grow >= NCOL) grow = NCOL - 1;
            float4 v = *(const float4*)(G + grow * 128 + kc * 32 + c4);
            Gs[(c4 + 0) * PITCH + r] = v.x; Gs[(c4 + 1) * PITCH + r] = v.y;
            Gs[(c4 + 2) * PITCH + r] = v.z; Gs[(c4 + 3) * PITCH + r] = v.w;
            float4 wv = *(const float4*)(W + (long)r * 128 + kc * 32 + c4);
            Ws[(c4 + 0) * PITCH + r] = wv.x; Ws[(c4 + 1) * PITCH + r] = wv.y;
            Ws[(c4 + 2) * PITCH + r] = wv.z; Ws[(c4 + 3) * PITCH + r] = wv.w;
        }
        __syncthreads();
        #pragma unroll
        for (int kk = 0; kk < 32; ++kk) {
            float4 a0 = *(const float4*)&Gs[kk * PITCH + ty * 8];
            float4 a1 = *(const float4*)&Gs[kk * PITCH + ty * 8 + 4];
            float4 b0 = *(const float4*)&Ws[kk * PITCH + tx * 8];
            float4 b1 = *(const float4*)&Ws[kk * PITCH + tx * 8 + 4];
            u64 ad[8] = {dup2(a0.x), dup2(a0.y), dup2(a0.z), dup2(a0.w),
                         dup2(a1.x), dup2(a1.y), dup2(a1.z), dup2(a1.w)};
            u64 bp4[4] = {pk2(b0.x, b0.y), pk2(b0.z, b0.w),
                          pk2(b1.x, b1.y), pk2(b1.z, b1.w)};
            #pragma unroll
            for (int i = 0; i < 8; ++i)
                #pragma unroll
                for (int j = 0; j < 4; ++j)
                    fma2(acc[i][j], ad[i], bp4[j]);
        }
        __syncthreads();
    }
    float bb0[8];
    {
        float4 b0 = *(const float4*)(bias + tx * 8);
        float4 b1 = *(const float4*)(bias + tx * 8 + 4);
        bb0[0] = b0.x; bb0[1] = b0.y; bb0[2] = b0.z; bb0[3] = b0.w;
        bb0[4] = b1.x; bb0[5] = b1.y; bb0[6] = b1.z; bb0[7] = b1.w;
    }
    #pragma unroll
    for (int i = 0; i < 8; ++i) {
        long row = r0 + ty * 8 + i;
        if (row >= NCOL) continue;
        float c[8];
        #pragma unroll
        for (int j = 0; j < 4; ++j) un2(acc[i][j], c[2 * j], c[2 * j + 1]);
        float4 v0 = {c[0] + bb0[0], c[1] + bb0[1], c[2] + bb0[2], c[3] + bb0[3]};
        float4 v1 = {c[4] + bb0[4], c[5] + bb0[5], c[6] + bb0[6], c[7] + bb0[7]};
        float* cp = C + row * 128 + tx * 8;
        *(float4*)(cp) = v0;
        *(float4*)(cp + 4) = v1;
    }
}

// ---------------------------------------------------------------------------
__global__ void zero_stats() {
    if (threadIdx.x < 8) g_stats[threadIdx.x] = 0.0;
}

// intra: pre[b][n][k][s] = Lf[(b*250+s)*32000 + n*250 + k]; tiled transpose + stats
__global__ void trans_stats_intra() {
    __shared__ float tile[32][33];
    __shared__ float rs[32], rq[32];
    int bn = blockIdx.y;
    int b = bn >> 7, n = bn & 127;
    int tk = blockIdx.x & 7, ts = blockIdx.x >> 3;
    int s = ts * 32 + threadIdx.y;
    int k = tk * 32 + threadIdx.x;
    float v = 0.f;
    if (s < 250 && k < 250)
        v = g_buf1[((long)(b * 250 + s)) * 32000 + n * 250 + k];
    tile[threadIdx.y][threadIdx.x] = v;
    __syncthreads();
    int k2 = tk * 32 + threadIdx.y;
    int s2 = ts * 32 + threadIdx.x;
    float wv = tile[threadIdx.x][threadIdx.y];
    bool ok = (k2 < 250 && s2 < 250);
    if (ok)
        g_buf2[(((long)bn * 250 + k2) * 250) + s2] = wv;
    float sum = ok ? wv : 0.f;
    float sq = sum * sum;
    #pragma unroll
    for (int off = 16; off; off >>= 1) {
        sum += __shfl_down_sync(0xffffffffu, sum, off);
        sq  += __shfl_down_sync(0xffffffffu, sq, off);
    }
    if (threadIdx.x == 0) { rs[threadIdx.y] = sum; rq[threadIdx.y] = sq; }
    __syncthreads();
    if (threadIdx.y == 0) {
        float a = rs[threadIdx.x], q = rq[threadIdx.x];
        #pragma unroll
        for (int off = 16; off; off >>= 1) {
            a += __shfl_down_sync(0xffffffffu, a, off);
            q += __shfl_down_sync(0xffffffffu, q, off);
        }
        if (threadIdx.x == 0) {
            atomicAdd(&g_stats[2 * b], (double)a);
            atomicAdd(&g_stats[2 * b + 1], (double)q);
        }
    }
}

// inter: pre[b][n][k][s] = Lf[(b*250+k)*32000 + n*250 + s]; coalesced copy + stats
__global__ void copy_stats_inter() {
    int i = blockIdx.x * 256 + threadIdx.x;
    int s = i % 250;
    int t = i / 250;
    int k = t % 250; t /= 250;
    int n = t & 127;
    int b = t >> 7;
    float v = g_buf1[((long)(b * 250 + k)) * 32000 + n * 250 + s];
    g_buf2[i] = v;
    float sum = v, sq = v * v;
    #pragma unroll
    for (int off = 16; off; off >>= 1) {
        sum += __shfl_down_sync(0xffffffffu, sum, off);
        sq  += __shfl_down_sync(0xffffffffu, sq, off);
    }
    __shared__ float ssum[8], ssq[8];
    int lane = threadIdx.x & 31, w = threadIdx.x >> 5;
    if (lane == 0) { ssum[w] = sum; ssq[w] = sq; }
    __syncthreads();
    if (threadIdx.x == 0) {
        float a = 0.f, q = 0.f;
        #pragma unroll
        for (int j = 0; j < 8; ++j) { a += ssum[j]; q += ssq[j]; }
        atomicAdd(&g_stats[2 * b], (double)a);
        atomicAdd(&g_stats[2 * b + 1], (double)q);
    }
}

// GroupNorm apply + residual; intra version also emits inter-path u (fused pack)
__global__ void norm_intra(const float* __restrict__ gg, const float* __restrict__ gb,
                           const float* __restrict__ x, float* __restrict__ out) {
    int i = blockIdx.x * 256 + threadIdx.x;
    int s = i % 250;
    int t = i / 250;
    int k = t % 250; t /= 250;
    int n = t & 127;
    int b = t >> 7;
    double mu  = g_stats[2 * b] / (double)PERB;
    double var = g_stats[2 * b + 1] / (double)PERB - mu * mu;
    float inv = (float)(1.0 / sqrt(var + 1e-8));
    float val = (g_buf2[i] - (float)mu) * inv * gg[n] + gb[n] + x[i];
    out[i] = val;
    g_buf0[(((long)(b * 250 + k)) * 128 + n) * 250 + s] = val;
}

__global__ void norm_final(const float* __restrict__ gg, const float* __restrict__ gb,
                           float* __restrict__ out) {
    int i = blockIdx.x * 256 + threadIdx.x;
    int n = (i / 62500) & 127;
    int b = i / PERB;
    double mu  = g_stats[2 * b] / (double)PERB;
    double var = g_stats[2 * b + 1] / (double)PERB - mu * mu;
    float inv = (float)(1.0 / sqrt(var + 1e-8));
    out[i] = (g_buf2[i] - (float)mu) * inv * gg[n] + gb[n] + out[i];
}

// ---------------------------------------------------------------------------
extern "C" void kernel_launch(void* const* d_in, const int* in_sizes, int n_in,
                              void* d_out, int out_size) {
    const float* x = (const float*)d_in[0];
    const float* ip[12];
    const float* pp[12];
    for (int j = 0; j < 12; ++j) ip[j] = (const float*)d_in[1 + j];
    for (int j = 0; j < 12; ++j) pp[j] = (const float*)d_in[13 + j];
    float* out = (float*)d_out;

    const int EB = TOT / 256;
    const int SMEM_OWGLU = (64 * PITCH + 128 * PITCH) * sizeof(float);  // ~99KB
    cudaFuncSetAttribute(gemm_ow_glu, cudaFuncAttributeMaxDynamicSharedMemorySize, SMEM_OWGLU);

    // ---- intra path ----
    pack_intra<<<dim3(64, 512), dim3(32, 32)>>>(x);
    kern_compute<<<NC, 256>>>(ip[0], ip[1], ip[2], ip[3], ip[4]);
    conv_gemm<<<dim3(16, 128), 256>>>(ip[5]);
    gemm_ow_glu<<<1954, 256, SMEM_OWGLU>>>(ip[6], ip[7]);
    gemm_lw<<<1954, 256>>>(ip[8], ip[9]);
    zero_stats<<<1, 32>>>();
    trans_stats_intra<<<dim3(64, 512), dim3(32, 32)>>>();
    norm_intra<<<EB, 256>>>(ip[10], ip[11], x, out);

    // ---- inter path ----
    kern_compute<<<NC, 256>>>(pp[0], pp[1], pp[2], pp[3], pp[4]);
    conv_gemm<<<dim3(16, 128), 256>>>(pp[5]);
    gemm_ow_glu<<<1954, 256, SMEM_OWGLU>>>(pp[6], pp[7]);
    gemm_lw<<<1954, 256>>>(pp[8], pp[9]);
    zero_stats<<<1, 32>>>();
    copy_stats_inter<<<EB, 256>>>();
    norm_final<<<EB, 256>>>(pp[10], pp[11], out);
}

// round 6
// speedup vs baseline: 1.1814x; 1.0726x over previous
#include <cuda_runtime.h>
#include <math.h>

#define NC    128
#define LL    250
#define MM    32
#define NCOL  250000
#define TOT   32000000
#define PERB  8000000
#define PITCH 132
#define PA    260

// Scratch
__device__ float g_buf0[32000000];  // u (packed) -> G (glu out, flat) -> u_inter
__device__ float g_buf1[32000000];  // yT -> Lf (lw out, flat)
__device__ float g_kern[NC * LL];
__device__ double g_stats[8];

// ---------------------------------------------------------------------------
typedef unsigned long long u64;
__device__ __forceinline__ u64 dup2(float x) {
    u64 r; asm("mov.b64 %0,{%1,%1};" : "=l"(r) : "f"(x)); return r;
}
__device__ __forceinline__ u64 pk2(float x, float y) {
    u64 r; asm("mov.b64 %0,{%1,%2};" : "=l"(r) : "f"(x), "f"(y)); return r;
}
__device__ __forceinline__ void fma2(u64& a, u64 b, u64 c) {
    asm("fma.rn.f32x2 %0,%1,%2,%0;" : "+l"(a) : "l"(b), "l"(c));
}
__device__ __forceinline__ void un2(u64 v, float& x, float& y) {
    asm("mov.b64 {%0,%1},%2;" : "=f"(x), "=f"(y) : "l"(v));
}

// ---------------------------------------------------------------------------
// Pack intra: u[(b*250+s)*128*250 + h*250 + k] = x[((b*128+h)*250 + k)*250 + s]
__global__ void pack_intra(const float* __restrict__ x) {
    __shared__ float tile[32][33];
    int bh = blockIdx.y;
    int b = bh >> 7, h = bh & 127;
    int tk = blockIdx.x & 7;
    int ts = blockIdx.x >> 3;
    int k = tk * 32 + threadIdx.y;
    int s = ts * 32 + threadIdx.x;
    if (k < 250 && s < 250)
        tile[threadIdx.y][threadIdx.x] = x[(((long)bh * 250 + k) * 250) + s];
    __syncthreads();
    int s2 = ts * 32 + threadIdx.y;
    int k2 = tk * 32 + threadIdx.x;
    if (s2 < 250 && k2 < 250)
        g_buf0[(((long)(b * 250 + s2) * 128 + h) * 250) + k2] = tile[threadIdx.x][threadIdx.y];
}

// ---------------------------------------------------------------------------
// S4D kernel synthesis
__global__ void kern_compute(const float* __restrict__ log_dt,
                             const float* __restrict__ logA_re,
                             const float* __restrict__ A_im,
                             const float* __restrict__ C_re,
                             const float* __restrict__ C_im) {
    __shared__ float sCr[MM], sCi[MM], sar[MM], sai[MM];
    int h = blockIdx.x;
    int t = threadIdx.x;
    if (t < MM) {
        float dt  = expf(log_dt[h]);
        float Are = -expf(logA_re[h * MM + t]);
        float Aim = A_im[h * MM + t];
        float ar = dt * Are, ai = dt * Aim;
        float ea = expf(ar);
        float sb, cb; sincosf(ai, &sb, &cb);
        float er = ea * cb - 1.f, ei = ea * sb;
        float den = Are * Are + Aim * Aim;
        float qr = (er * Are + ei * Aim) / den;
        float qi = (ei * Are - er * Aim) / den;
        float cr = C_re[h * MM + t], ci = C_im[h * MM + t];
        sCr[t] = cr * qr - ci * qi;
        sCi[t] = cr * qi + ci * qr;
        sar[t] = ar; sai[t] = ai;
    }
    __syncthreads();
    if (t < LL) {
        float fl = (float)t;
        float sum = 0.f;
        #pragma unroll
        for (int m = 0; m < MM; ++m) {
            float ea = expf(sar[m] * fl);
            float sb, cb; sincosf(sai[m] * fl, &sb, &cb);
            sum += ea * (sCr[m] * cb - sCi[m] * sb);
        }
        g_kern[h * LL + t] = 2.f * sum;
    }
}

// ---------------------------------------------------------------------------
// Conv as per-h Toeplitz GEMM + D*u + GELU.
__global__ void __launch_bounds__(256, 2)
conv_gemm(const float* __restrict__ D) {
    __shared__ float As[32 * PITCH];
    __shared__ float Bs[32 * PITCH];
    __shared__ float skp[512];
    int tid = threadIdx.x;
    int h = blockIdx.y;
    int rowblk = blockIdx.x >> 1, colblk = blockIdx.x & 1;
    int r0 = rowblk * 128;
    int t0 = colblk * 128;
    int nkt = colblk ? 8 : 4;

    skp[tid] = 0.f;
    skp[256 + tid] = (tid < 250) ? g_kern[h * 250 + tid] : 0.f;
    __syncthreads();

    int tx = tid & 15, ty = tid >> 4;
    u64 acc[8][4];
    #pragma unroll
    for (int i = 0; i < 8; ++i)
        #pragma unroll
        for (int j = 0; j < 4; ++j) acc[i][j] = 0ull;

    for (int kt = 0; kt < nkt; ++kt) {
        int m0 = kt * 32;
        {
            int c4 = (tid & 7) * 4;
            int rb = tid >> 3;
            #pragma unroll
            for (int p = 0; p < 4; ++p) {
                int r = rb + p * 32;
                int bb = r0 + r; if (bb > 999) bb = 999;
                const float* up = g_buf0 + ((long)bb * 128 + h) * 250 + m0 + c4;
                float2 v0 = (m0 + c4     < 250) ? *(const float2*)(up)     : make_float2(0.f, 0.f);
                float2 v1 = (m0 + c4 + 2 < 250) ? *(const float2*)(up + 2) : make_float2(0.f, 0.f);
                As[(c4 + 0) * PITCH + r] = v0.x; As[(c4 + 1) * PITCH + r] = v0.y;
                As[(c4 + 2) * PITCH + r] = v1.x; As[(c4 + 3) * PITCH + r] = v1.y;
            }
        }
        {
            int mm = tid >> 3;
            int ttb = (tid & 7) * 16;
            int base = 256 + t0 - m0 - mm + ttb;
            #pragma unroll
            for (int q = 0; q < 16; ++q)
                Bs[mm * PITCH + ttb + q] = skp[base + q];
        }
        __syncthreads();
        #pragma unroll
        for (int kk = 0; kk < 32; ++kk) {
            float4 a0 = *(const float4*)&As[kk * PITCH + ty * 8];
            float4 a1 = *(const float4*)&As[kk * PITCH + ty * 8 + 4];
            float4 b0 = *(const float4*)&Bs[kk * PITCH + tx * 8];
            float4 b1 = *(const float4*)&Bs[kk * PITCH + tx * 8 + 4];
            u64 ad[8] = {dup2(a0.x), dup2(a0.y), dup2(a0.z), dup2(a0.w),
                         dup2(a1.x), dup2(a1.y), dup2(a1.z), dup2(a1.w)};
            u64 bp4[4] = {pk2(b0.x, b0.y), pk2(b0.z, b0.w),
                          pk2(b1.x, b1.y), pk2(b1.z, b1.w)};
            #pragma unroll
            for (int i = 0; i < 8; ++i)
                #pragma unroll
                for (int j = 0; j < 4; ++j)
                    fma2(acc[i][j], ad[i], bp4[j]);
        }
        __syncthreads();
    }

    float dh = D[h];
    #pragma unroll
    for (int i = 0; i < 8; ++i) {
        int bb = r0 + ty * 8 + i;
        if (bb > 999) continue;
        float c[8];
        #pragma unroll
        for (int j = 0; j < 4; ++j) un2(acc[i][j], c[2 * j], c[2 * j + 1]);
        int tbase = t0 + tx * 8;
        const float* up = g_buf0 + ((long)bb * 128 + h) * 250 + tbase;
        float* yp = g_buf1 + (long)h * NCOL + (long)bb * 250 + tbase;
        #pragma unroll
        for (int j2 = 0; j2 < 4; ++j2) {
            int t = tbase + 2 * j2;
            if (t < 250) {
                float2 uv = *(const float2*)(up + 2 * j2);
                float y0 = c[2 * j2]     + dh * uv.x;
                float y1 = c[2 * j2 + 1] + dh * uv.y;
                float e0 = y0 + 0.044715f * y0 * y0 * y0;
                float e1 = y1 + 0.044715f * y1 * y1 * y1;
                float2 g;
                g.x = 0.5f * y0 * (1.f + tanhf(0.7978845608f * e0));
                g.y = 0.5f * y1 * (1.f + tanhf(0.7978845608f * e1));
                *(float2*)(yp + 2 * j2) = g;
            }
        }
    }
}

// ---------------------------------------------------------------------------
// Fused ow GEMM + GLU, single-pass 256x128 tile, 512 threads.
// Thread ty (0..31) owns rows {ty*4+i} (z1) and {128+ty*4+i} (z2) -> GLU local.
__global__ void __launch_bounds__(512, 1)
gemm_ow_glu(const float* __restrict__ A, const float* __restrict__ bias) {
    extern __shared__ float sm[];
    float* As = sm;                 // [32][PA]  rows m 0..255
    float* Bs = sm + 32 * PA;       // [32][PITCH]
    const float* __restrict__ Bm = g_buf1;

    int tid = threadIdx.x;
    int tx = tid & 15, ty = tid >> 4;   // ty 0..31
    long n0 = (long)blockIdx.x * 128;

    u64 acc[8][4];
    #pragma unroll
    for (int i = 0; i < 8; ++i)
        #pragma unroll
        for (int j = 0; j < 4; ++j) acc[i][j] = 0ull;

    for (int kc = 0; kc < 4; ++kc) {
        // A tile: 256 rows x 32 k, transposed store
        {
            int c4 = (tid & 7) * 4;
            int rb = tid >> 3;          // 0..63
            #pragma unroll
            for (int p = 0; p < 4; ++p) {
                int r = rb + p * 64;
                float4 v = *(const float4*)(A + (long)r * 128 + kc * 32 + c4);
                As[(c4 + 0) * PA + r] = v.x; As[(c4 + 1) * PA + r] = v.y;
                As[(c4 + 2) * PA + r] = v.z; As[(c4 + 3) * PA + r] = v.w;
            }
        }
        // B tile: 32 k x 128 n
        {
            int n4 = (tid & 31) * 4;
            int kb = tid >> 5;          // 0..15
            #pragma unroll
            for (int p = 0; p < 2; ++p) {
                int kr = kb + p * 16;
                long col = n0 + n4;
                const float* bp = Bm + (long)(kc * 32 + kr) * NCOL + col;
                float4 v;
                if (col + 4 <= NCOL) v = *(const float4*)bp;
                else {
                    v.x = (col + 0 < NCOL) ? bp[0] : 0.f;
                    v.y = (col + 1 < NCOL) ? bp[1] : 0.f;
                    v.z = (col + 2 < NCOL) ? bp[2] : 0.f;
                    v.w = (col + 3 < NCOL) ? bp[3] : 0.f;
                }
                *(float4*)&Bs[kr * PITCH + n4] = v;
            }
        }
        __syncthreads();
        #pragma unroll
        for (int kk = 0; kk < 32; ++kk) {
            float4 a0 = *(const float4*)&As[kk * PA + ty * 4];
            float4 a1 = *(const float4*)&As[kk * PA + 128 + ty * 4];
            float4 b0 = *(const float4*)&Bs[kk * PITCH + tx * 8];
            float4 b1 = *(const float4*)&Bs[kk * PITCH + tx * 8 + 4];
            u64 ad[8] = {dup2(a0.x), dup2(a0.y), dup2(a0.z), dup2(a0.w),
                         dup2(a1.x), dup2(a1.y), dup2(a1.z), dup2(a1.w)};
            u64 bp4[4] = {pk2(b0.x, b0.y), pk2(b0.z, b0.w),
                          pk2(b1.x, b1.y), pk2(b1.z, b1.w)};
            #pragma unroll
            for (int i = 0; i < 8; ++i)
                #pragma unroll
                for (int j = 0; j < 4; ++j)
                    fma2(acc[i][j], ad[i], bp4[j]);
        }
        __syncthreads();
    }

    // GLU epilogue: acc[i] = z1 rows (o = ty*4+i), acc[4+i] = z2 rows (o+128)
    #pragma unroll
    for (int i = 0; i < 4; ++i) {
        int o = ty * 4 + i;
        float b1v = bias[o], b2v = bias[128 + o];
        float c1[8], c2[8];
        #pragma unroll
        for (int j = 0; j < 4; ++j) {
            un2(acc[i][j],     c1[2 * j], c1[2 * j + 1]);
            un2(acc[4 + i][j], c2[2 * j], c2[2 * j + 1]);
        }
        #pragma unroll
        for (int j = 0; j < 8; ++j) {
            long col = n0 + tx * 8 + j;
            if (col < NCOL) {
                float z1 = c1[j] + b1v;
                float z2 = c2[j] + b2v;
                float g = z1 / (1.f + expf(-z2));
                int bb = (int)(col / 250);
                int l  = (int)(col - (long)bb * 250);
                g_buf0[((long)bb * 128 + o) * 250 + l] = g;
            }
        }
    }
}

// ---------------------------------------------------------------------------
// GEMM2 (lw) + fused groupnorm stats (block reduce + atomicAdd).
__global__ void __launch_bounds__(256, 2)
gemm_lw(const float* __restrict__ W, const float* __restrict__ bias) {
    const float* __restrict__ G = g_buf0;
    float* __restrict__ C = g_buf1;
    __shared__ float Gs[32 * PITCH];
    __shared__ float Ws[32 * PITCH];

    int tid = threadIdx.x;
    int tx = tid & 15, ty = tid >> 4;
    long r0 = (long)blockIdx.x * 128;

    u64 acc[8][4];
    #pragma unroll
    for (int i = 0; i < 8; ++i)
        #pragma unroll
        for (int j = 0; j < 4; ++j) acc[i][j] = 0ull;

    for (int kc = 0; kc < 4; ++kc) {
        int c4 = (tid & 7) * 4;
        int rb = tid >> 3;
        #pragma unroll
        for (int p = 0; p < 4; ++p) {
            int r = rb + p * 32;
            long grow = r0 + r;
            if (grow >= NCOL) grow = NCOL - 1;
            float4 v = *(const float4*)(G + grow * 128 + kc * 32 + c4);
            Gs[(c4 + 0) * PITCH + r] = v.x; Gs[(c4 + 1) * PITCH + r] = v.y;
            Gs[(c4 + 2) * PITCH + r] = v.z; Gs[(c4 + 3) * PITCH + r] = v.w;
            float4 wv = *(const float4*)(W + (long)r * 128 + kc * 32 + c4);
            Ws[(c4 + 0) * PITCH + r] = wv.x; Ws[(c4 + 1) * PITCH + r] = wv.y;
            Ws[(c4 + 2) * PITCH + r] = wv.z; Ws[(c4 + 3) * PITCH + r] = wv.w;
        }
        __syncthreads();
        #pragma unroll
        for (int kk = 0; kk < 32; ++kk) {
            float4 a0 = *(const float4*)&Gs[kk * PITCH + ty * 8];
            float4 a1 = *(const float4*)&Gs[kk * PITCH + ty * 8 + 4];
            float4 b0 = *(const float4*)&Ws[kk * PITCH + tx * 8];
            float4 b1 = *(const float4*)&Ws[kk * PITCH + tx * 8 + 4];
            u64 ad[8] = {dup2(a0.x), dup2(a0.y), dup2(a0.z), dup2(a0.w),
                         dup2(a1.x), dup2(a1.y), dup2(a1.z), dup2(a1.w)};
            u64 bp4[4] = {pk2(b0.x, b0.y), pk2(b0.z, b0.w),
                          pk2(b1.x, b1.y), pk2(b1.z, b1.w)};
            #pragma unroll
            for (int i = 0; i < 8; ++i)
                #pragma unroll
                for (int j = 0; j < 4; ++j)
                    fma2(acc[i][j], ad[i], bp4[j]);
        }
        __syncthreads();
    }
    float bb0[8];
    {
        float4 b0 = *(const float4*)(bias + tx * 8);
        float4 b1 = *(const float4*)(bias + tx * 8 + 4);
        bb0[0] = b0.x; bb0[1] = b0.y; bb0[2] = b0.z; bb0[3] = b0.w;
        bb0[4] = b1.x; bb0[5] = b1.y; bb0[6] = b1.z; bb0[7] = b1.w;
    }
    int b0idx = (int)(r0 / 62500);   // rows-per-batch = 62500
    float s0 = 0.f, q0 = 0.f, s1 = 0.f, q1 = 0.f;
    #pragma unroll
    for (int i = 0; i < 8; ++i) {
        long row = r0 + ty * 8 + i;
        if (row >= NCOL) continue;
        float c[8];
        #pragma unroll
        for (int j = 0; j < 4; ++j) un2(acc[i][j], c[2 * j], c[2 * j + 1]);
        float rs = 0.f, rq = 0.f;
        #pragma unroll
        for (int j = 0; j < 8; ++j) {
            float v = c[j] + bb0[j];
            c[j] = v;
            rs += v; rq += v * v;
        }
        if ((int)(row / 62500) == b0idx) { s0 += rs; q0 += rq; }
        else                             { s1 += rs; q1 += rq; }
        float4 v0 = {c[0], c[1], c[2], c[3]};
        float4 v1 = {c[4], c[5], c[6], c[7]};
        float* cp = C + row * 128 + tx * 8;
        *(float4*)(cp) = v0;
        *(float4*)(cp + 4) = v1;
    }
    // stats reduction
    #pragma unroll
    for (int off = 16; off; off >>= 1) {
        s0 += __shfl_down_sync(0xffffffffu, s0, off);
        q0 += __shfl_down_sync(0xffffffffu, q0, off);
        s1 += __shfl_down_sync(0xffffffffu, s1, off);
        q1 += __shfl_down_sync(0xffffffffu, q1, off);
    }
    __shared__ float red[8][4];
    int lane = tid & 31, w = tid >> 5;
    if (lane == 0) { red[w][0] = s0; red[w][1] = q0; red[w][2] = s1; red[w][3] = q1; }
    __syncthreads();
    if (tid == 0) {
        float ts0 = 0.f, tq0 = 0.f, ts1 = 0.f, tq1 = 0.f;
        #pragma unroll
        for (int j = 0; j < 8; ++j) {
            ts0 += red[j][0]; tq0 += red[j][1];
            ts1 += red[j][2]; tq1 += red[j][3];
        }
        atomicAdd(&g_stats[2 * b0idx],     (double)ts0);
        atomicAdd(&g_stats[2 * b0idx + 1], (double)tq0);
        if (b0idx < 3) {
            atomicAdd(&g_stats[2 * b0idx + 2], (double)ts1);
            atomicAdd(&g_stats[2 * b0idx + 3], (double)tq1);
        }
    }
}

// ---------------------------------------------------------------------------
__global__ void zero_stats() {
    if (threadIdx.x < 8) g_stats[threadIdx.x] = 0.0;
}

// intra: fused transpose + groupnorm + residual + inter-u emit.
// out[b][n][k][s] = gn(Lf[(b*250+s)*32000 + n*250 + k]) + x[b][n][k][s]
__global__ void trans_norm_intra(const float* __restrict__ gg, const float* __restrict__ gb,
                                 const float* __restrict__ x, float* __restrict__ out) {
    __shared__ float tile[32][33];
    int bn = blockIdx.y;
    int b = bn >> 7, n = bn & 127;
    int tk = blockIdx.x & 7, ts = blockIdx.x >> 3;
    int s = ts * 32 + threadIdx.y;
    int k = tk * 32 + threadIdx.x;
    if (s < 250 && k < 250)
        tile[threadIdx.y][threadIdx.x] =
            g_buf1[((long)(b * 250 + s)) * 32000 + n * 250 + k];
    __syncthreads();
    int k2 = tk * 32 + threadIdx.y;
    int s2 = ts * 32 + threadIdx.x;
    if (k2 < 250 && s2 < 250) {
        double mu  = g_stats[2 * b] / (double)PERB;
        double var = g_stats[2 * b + 1] / (double)PERB - mu * mu;
        float inv = (float)(1.0 / sqrt(var + 1e-8));
        long oi = (((long)(b * 128 + n)) * 250 + k2) * 250 + s2;
        float val = (tile[threadIdx.x][threadIdx.y] - (float)mu) * inv * gg[n] + gb[n] + x[oi];
        out[oi] = val;
        g_buf0[(((long)(b * 250 + k2)) * 128 + n) * 250 + s2] = val;
    }
}

// inter: out[i] += gn(Lf[(b*250+k)*32000 + n*250 + s])   (direct read)
__global__ void norm_final(const float* __restrict__ gg, const float* __restrict__ gb,
                           float* __restrict__ out) {
    int i = blockIdx.x * 256 + threadIdx.x;
    int s = i % 250;
    int t = i / 250;
    int k = t % 250; t /= 250;
    int n = t & 127;
    int b = t >> 7;
    double mu  = g_stats[2 * b] / (double)PERB;
    double var = g_stats[2 * b + 1] / (double)PERB - mu * mu;
    float inv = (float)(1.0 / sqrt(var + 1e-8));
    float v = g_buf1[((long)(b * 250 + k)) * 32000 + n * 250 + s];
    out[i] = (v - (float)mu) * inv * gg[n] + gb[n] + out[i];
}

// ---------------------------------------------------------------------------
extern "C" void kernel_launch(void* const* d_in, const int* in_sizes, int n_in,
                              void* d_out, int out_size) {
    const float* x = (const float*)d_in[0];
    const float* ip[12];
    const float* pp[12];
    for (int j = 0; j < 12; ++j) ip[j] = (const float*)d_in[1 + j];
    for (int j = 0; j < 12; ++j) pp[j] = (const float*)d_in[13 + j];
    float* out = (float*)d_out;

    const int EB = TOT / 256;
    const int SMEM_OW = (32 * PA + 32 * PITCH) * sizeof(float);  // ~50KB
    cudaFuncSetAttribute(gemm_ow_glu, cudaFuncAttributeMaxDynamicSharedMemorySize, SMEM_OW);

    // ---- intra path ----
    pack_intra<<<dim3(64, 512), dim3(32, 32)>>>(x);
    kern_compute<<<NC, 256>>>(ip[0], ip[1], ip[2], ip[3], ip[4]);
    conv_gemm<<<dim3(16, 128), 256>>>(ip[5]);
    gemm_ow_glu<<<1954, 512, SMEM_OW>>>(ip[6], ip[7]);
    zero_stats<<<1, 32>>>();
    gemm_lw<<<1954, 256>>>(ip[8], ip[9]);
    trans_norm_intra<<<dim3(64, 512), dim3(32, 32)>>>(ip[10], ip[11], x, out);

    // ---- inter path ----
    kern_compute<<<NC, 256>>>(pp[0], pp[1], pp[2], pp[3], pp[4]);
    conv_gemm<<<dim3(16, 128), 256>>>(pp[5]);
    gemm_ow_glu<<<1954, 512, SMEM_OW>>>(pp[6], pp[7]);
    zero_stats<<<1, 32>>>();
    gemm_lw<<<1954, 256>>>(pp[8], pp[9]);
    norm_final<<<EB, 256>>>(pp[10], pp[11], out);
}

// round 7
// speedup vs baseline: 2.8594x; 2.4204x over previous
#include <cuda_runtime.h>
#include <math.h>

#define NC    128
#define LL    250
#define MM    32
#define NCOL  250000
#define TOT   32000000
#define PERB  8000000
#define PITCH 132

// Scratch
__device__ float g_buf0[32000000];  // u (packed) -> G (glu out, flat) -> u_inter
__device__ float g_buf1[32000000];  // yT -> Lf (lw out, flat)
__device__ float g_kern[NC * LL];
__device__ double g_stats[8];
__device__ float g_mu[4], g_inv[4];

// ---------------------------------------------------------------------------
typedef unsigned long long u64;
__device__ __forceinline__ u64 dup2(float x) {
    u64 r; asm("mov.b64 %0,{%1,%1};" : "=l"(r) : "f"(x)); return r;
}
__device__ __forceinline__ u64 pk2(float x, float y) {
    u64 r; asm("mov.b64 %0,{%1,%2};" : "=l"(r) : "f"(x), "f"(y)); return r;
}
__device__ __forceinline__ void fma2(u64& a, u64 b, u64 c) {
    asm("fma.rn.f32x2 %0,%1,%2,%0;" : "+l"(a) : "l"(b), "l"(c));
}
__device__ __forceinline__ void un2(u64 v, float& x, float& y) {
    asm("mov.b64 {%0,%1},%2;" : "=f"(x), "=f"(y) : "l"(v));
}

// ---------------------------------------------------------------------------
__global__ void pack_intra(const float* __restrict__ x) {
    __shared__ float tile[32][33];
    int bh = blockIdx.y;
    int b = bh >> 7, h = bh & 127;
    int tk = blockIdx.x & 7;
    int ts = blockIdx.x >> 3;
    int k = tk * 32 + threadIdx.y;
    int s = ts * 32 + threadIdx.x;
    if (k < 250 && s < 250)
        tile[threadIdx.y][threadIdx.x] = x[(((long)bh * 250 + k) * 250) + s];
    __syncthreads();
    int s2 = ts * 32 + threadIdx.y;
    int k2 = tk * 32 + threadIdx.x;
    if (s2 < 250 && k2 < 250)
        g_buf0[(((long)(b * 250 + s2) * 128 + h) * 250) + k2] = tile[threadIdx.x][threadIdx.y];
}

// ---------------------------------------------------------------------------
__global__ void kern_compute(const float* __restrict__ log_dt,
                             const float* __restrict__ logA_re,
                             const float* __restrict__ A_im,
                             const float* __restrict__ C_re,
                             const float* __restrict__ C_im) {
    __shared__ float sCr[MM], sCi[MM], sar[MM], sai[MM];
    int h = blockIdx.x;
    int t = threadIdx.x;
    if (t < MM) {
        float dt  = expf(log_dt[h]);
        float Are = -expf(logA_re[h * MM + t]);
        float Aim = A_im[h * MM + t];
        float ar = dt * Are, ai = dt * Aim;
        float ea = expf(ar);
        float sb, cb; sincosf(ai, &sb, &cb);
        float er = ea * cb - 1.f, ei = ea * sb;
        float den = Are * Are + Aim * Aim;
        float qr = (er * Are + ei * Aim) / den;
        float qi = (ei * Are - er * Aim) / den;
        float cr = C_re[h * MM + t], ci = C_im[h * MM + t];
        sCr[t] = cr * qr - ci * qi;
        sCi[t] = cr * qi + ci * qr;
        sar[t] = ar; sai[t] = ai;
    }
    __syncthreads();
    if (t < LL) {
        float fl = (float)t;
        float sum = 0.f;
        #pragma unroll
        for (int m = 0; m < MM; ++m) {
            float ea = expf(sar[m] * fl);
            float sb, cb; sincosf(sai[m] * fl, &sb, &cb);
            sum += ea * (sCr[m] * cb - sCi[m] * sb);
        }
        g_kern[h * LL + t] = 2.f * sum;
    }
}

// ---------------------------------------------------------------------------
// Conv as per-h Toeplitz GEMM + D*u + GELU.
__global__ void __launch_bounds__(256, 2)
conv_gemm(const float* __restrict__ D) {
    __shared__ float As[32 * PITCH];
    __shared__ float Bs[32 * PITCH];
    __shared__ float skp[512];
    int tid = threadIdx.x;
    int h = blockIdx.y;
    int rowblk = blockIdx.x >> 1, colblk = blockIdx.x & 1;
    int r0 = rowblk * 128;
    int t0 = colblk * 128;
    int nkt = colblk ? 8 : 4;

    skp[tid] = 0.f;
    skp[256 + tid] = (tid < 250) ? g_kern[h * 250 + tid] : 0.f;
    __syncthreads();

    int tx = tid & 15, ty = tid >> 4;
    u64 acc[8][4];
    #pragma unroll
    for (int i = 0; i < 8; ++i)
        #pragma unroll
        for (int j = 0; j < 4; ++j) acc[i][j] = 0ull;

    for (int kt = 0; kt < nkt; ++kt) {
        int m0 = kt * 32;
        {
            int c4 = (tid & 7) * 4;
            int rb = tid >> 3;
            #pragma unroll
            for (int p = 0; p < 4; ++p) {
                int r = rb + p * 32;
                int bb = r0 + r; if (bb > 999) bb = 999;
                const float* up = g_buf0 + ((long)bb * 128 + h) * 250 + m0 + c4;
                float2 v0 = (m0 + c4     < 250) ? *(const float2*)(up)     : make_float2(0.f, 0.f);
                float2 v1 = (m0 + c4 + 2 < 250) ? *(const float2*)(up + 2) : make_float2(0.f, 0.f);
                As[(c4 + 0) * PITCH + r] = v0.x; As[(c4 + 1) * PITCH + r] = v0.y;
                As[(c4 + 2) * PITCH + r] = v1.x; As[(c4 + 3) * PITCH + r] = v1.y;
            }
        }
        {
            int mm = tid >> 3;
            int ttb = (tid & 7) * 16;
            int base = 256 + t0 - m0 - mm + ttb;
            #pragma unroll
            for (int q = 0; q < 16; ++q)
                Bs[mm * PITCH + ttb + q] = skp[base + q];
        }
        __syncthreads();
        #pragma unroll
        for (int kk = 0; kk < 32; ++kk) {
            float4 a0 = *(const float4*)&As[kk * PITCH + ty * 8];
            float4 a1 = *(const float4*)&As[kk * PITCH + ty * 8 + 4];
            float4 b0 = *(const float4*)&Bs[kk * PITCH + tx * 8];
            float4 b1 = *(const float4*)&Bs[kk * PITCH + tx * 8 + 4];
            u64 ad[8] = {dup2(a0.x), dup2(a0.y), dup2(a0.z), dup2(a0.w),
                         dup2(a1.x), dup2(a1.y), dup2(a1.z), dup2(a1.w)};
            u64 bp4[4] = {pk2(b0.x, b0.y), pk2(b0.z, b0.w),
                          pk2(b1.x, b1.y), pk2(b1.z, b1.w)};
            #pragma unroll
            for (int i = 0; i < 8; ++i)
                #pragma unroll
                for (int j = 0; j < 4; ++j)
                    fma2(acc[i][j], ad[i], bp4[j]);
        }
        __syncthreads();
    }

    float dh = D[h];
    #pragma unroll
    for (int i = 0; i < 8; ++i) {
        int bb = r0 + ty * 8 + i;
        if (bb > 999) continue;
        float c[8];
        #pragma unroll
        for (int j = 0; j < 4; ++j) un2(acc[i][j], c[2 * j], c[2 * j + 1]);
        int tbase = t0 + tx * 8;
        const float* up = g_buf0 + ((long)bb * 128 + h) * 250 + tbase;
        float* yp = g_buf1 + (long)h * NCOL + (long)bb * 250 + tbase;
        #pragma unroll
        for (int j2 = 0; j2 < 4; ++j2) {
            int t = tbase + 2 * j2;
            if (t < 250) {
                float2 uv = *(const float2*)(up + 2 * j2);
                float y0 = c[2 * j2]     + dh * uv.x;
                float y1 = c[2 * j2 + 1] + dh * uv.y;
                float e0 = y0 + 0.044715f * y0 * y0 * y0;
                float e1 = y1 + 0.044715f * y1 * y1 * y1;
                float2 g;
                g.x = 0.5f * y0 * (1.f + tanhf(0.7978845608f * e0));
                g.y = 0.5f * y1 * (1.f + tanhf(0.7978845608f * e1));
                *(float2*)(yp + 2 * j2) = g;
            }
        }
    }
}

// ---------------------------------------------------------------------------
// Fused ow GEMM + GLU (two row-phases; phase 0 stashed in smem). R3 version.
__global__ void __launch_bounds__(256, 2)
gemm_ow_glu(const float* __restrict__ A, const float* __restrict__ bias) {
    extern __shared__ float sm[];
    float* As = sm;                    // [32][PITCH]
    float* Bs = sm + 32 * PITCH;       // [32][PITCH]
    float* Zs = sm + 64 * PITCH;       // [128][PITCH]
    const float* __restrict__ Bm = g_buf1;

    int tid = threadIdx.x;
    int tx = tid & 15, ty = tid >> 4;
    long n0 = (long)blockIdx.x * 128;

    for (int phase = 0; phase < 2; ++phase) {
        int m0 = phase * 128;
        u64 acc[8][4];
        #pragma unroll
        for (int i = 0; i < 8; ++i)
            #pragma unroll
            for (int j = 0; j < 4; ++j) acc[i][j] = 0ull;

        for (int kc = 0; kc < 4; ++kc) {
            {
                int c4 = (tid & 7) * 4;
                int rb = tid >> 3;
                #pragma unroll
                for (int p = 0; p < 4; ++p) {
                    int r = rb + p * 32;
                    float4 v = *(const float4*)(A + (long)(m0 + r) * 128 + kc * 32 + c4);
                    As[(c4 + 0) * PITCH + r] = v.x; As[(c4 + 1) * PITCH + r] = v.y;
                    As[(c4 + 2) * PITCH + r] = v.z; As[(c4 + 3) * PITCH + r] = v.w;
                }
            }
            {
                int n4 = (tid & 31) * 4;
                int kb = tid >> 5;
                #pragma unroll
                for (int p = 0; p < 4; ++p) {
                    int kr = kb + p * 8;
                    long col = n0 + n4;
                    const float* bp = Bm + (long)(kc * 32 + kr) * NCOL + col;
                    float4 v;
                    if (col + 4 <= NCOL) v = *(const float4*)bp;
                    else {
                        v.x = (col + 0 < NCOL) ? bp[0] : 0.f;
                        v.y = (col + 1 < NCOL) ? bp[1] : 0.f;
                        v.z = (col + 2 < NCOL) ? bp[2] : 0.f;
                        v.w = (col + 3 < NCOL) ? bp[3] : 0.f;
                    }
                    *(float4*)&Bs[kr * PITCH + n4] = v;
                }
            }
            __syncthreads();
            #pragma unroll
            for (int kk = 0; kk < 32; ++kk) {
                float4 a0 = *(const float4*)&As[kk * PITCH + ty * 8];
                float4 a1 = *(const float4*)&As[kk * PITCH + ty * 8 + 4];
                float4 b0 = *(const float4*)&Bs[kk * PITCH + tx * 8];
                float4 b1 = *(const float4*)&Bs[kk * PITCH + tx * 8 + 4];
                u64 ad[8] = {dup2(a0.x), dup2(a0.y), dup2(a0.z), dup2(a0.w),
                             dup2(a1.x), dup2(a1.y), dup2(a1.z), dup2(a1.w)};
                u64 bp4[4] = {pk2(b0.x, b0.y), pk2(b0.z, b0.w),
                              pk2(b1.x, b1.y), pk2(b1.z, b1.w)};
                #pragma unroll
                for (int i = 0; i < 8; ++i)
                    #pragma unroll
                    for (int j = 0; j < 4; ++j)
                        fma2(acc[i][j], ad[i], bp4[j]);
            }
            __syncthreads();
        }

        if (phase == 0) {
            #pragma unroll
            for (int i = 0; i < 8; ++i) {
                int row = ty * 8 + i;
                float bv = bias[row];
                float c[8];
                #pragma unroll
                for (int j = 0; j < 4; ++j) un2(acc[i][j], c[2 * j], c[2 * j + 1]);
                float4 v0 = {c[0] + bv, c[1] + bv, c[2] + bv, c[3] + bv};
                float4 v1 = {c[4] + bv, c[5] + bv, c[6] + bv, c[7] + bv};
                *(float4*)&Zs[row * PITCH + tx * 8]     = v0;
                *(float4*)&Zs[row * PITCH + tx * 8 + 4] = v1;
            }
        } else {
            #pragma unroll
            for (int i = 0; i < 8; ++i) {
                int o = ty * 8 + i;
                float bv = bias[128 + o];
                float c[8];
                #pragma unroll
                for (int j = 0; j < 4; ++j) un2(acc[i][j], c[2 * j], c[2 * j + 1]);
                #pragma unroll
                for (int j = 0; j < 8; ++j) {
                    long col = n0 + tx * 8 + j;
                    if (col < NCOL) {
                        float z1 = Zs[o * PITCH + tx * 8 + j];
                        float z2 = c[j] + bv;
                        float g = z1 / (1.f + expf(-z2));
                        int bb = (int)(col / 250);
                        int l  = (int)(col - (long)bb * 250);
                        g_buf0[((long)bb * 128 + o) * 250 + l] = g;
                    }
                }
            }
        }
        __syncthreads();
    }
}

// ---------------------------------------------------------------------------
// GEMM2 (lw) + fused groupnorm stats.
__global__ void __launch_bounds__(256, 2)
gemm_lw(const float* __restrict__ W, const float* __restrict__ bias) {
    const float* __restrict__ G = g_buf0;
    float* __restrict__ C = g_buf1;
    __shared__ float Gs[32 * PITCH];
    __shared__ float Ws[32 * PITCH];

    int tid = threadIdx.x;
    int tx = tid & 15, ty = tid >> 4;
    long r0 = (long)blockIdx.x * 128;

    u64 acc[8][4];
    #pragma unroll
    for (int i = 0; i < 8; ++i)
        #pragma unroll
        for (int j = 0; j < 4; ++j) acc[i][j] = 0ull;

    for (int kc = 0; kc < 4; ++kc) {
        int c4 = (tid & 7) * 4;
        int rb = tid >> 3;
        #pragma unroll
        for (int p = 0; p < 4; ++p) {
            int r = rb + p * 32;
            long grow = r0 + r;
            if (grow >= NCOL) grow = NCOL - 1;
            float4 v = *(const float4*)(G + grow * 128 + kc * 32 + c4);
            Gs[(c4 + 0) * PITCH + r] = v.x; Gs[(c4 + 1) * PITCH + r] = v.y;
            Gs[(c4 + 2) * PITCH + r] = v.z; Gs[(c4 + 3) * PITCH + r] = v.w;
            float4 wv = *(const float4*)(W + (long)r * 128 + kc * 32 + c4);
            Ws[(c4 + 0) * PITCH + r] = wv.x; Ws[(c4 + 1) * PITCH + r] = wv.y;
            Ws[(c4 + 2) * PITCH + r] = wv.z; Ws[(c4 + 3) * PITCH + r] = wv.w;
        }
        __syncthreads();
        #pragma unroll
        for (int kk = 0; kk < 32; ++kk) {
            float4 a0 = *(const float4*)&Gs[kk * PITCH + ty * 8];
            float4 a1 = *(const float4*)&Gs[kk * PITCH + ty * 8 + 4];
            float4 b0 = *(const float4*)&Ws[kk * PITCH + tx * 8];
            float4 b1 = *(const float4*)&Ws[kk * PITCH + tx * 8 + 4];
            u64 ad[8] = {dup2(a0.x), dup2(a0.y), dup2(a0.z), dup2(a0.w),
                         dup2(a1.x), dup2(a1.y), dup2(a1.z), dup2(a1.w)};
            u64 bp4[4] = {pk2(b0.x, b0.y), pk2(b0.z, b0.w),
                          pk2(b1.x, b1.y), pk2(b1.z, b1.w)};
            #pragma unroll
            for (int i = 0; i < 8; ++i)
                #pragma unroll
                for (int j = 0; j < 4; ++j)
                    fma2(acc[i][j], ad[i], bp4[j]);
        }
        __syncthreads();
    }
    float bb0[8];
    {
        float4 b0 = *(const float4*)(bias + tx * 8);
        float4 b1 = *(const float4*)(bias + tx * 8 + 4);
        bb0[0] = b0.x; bb0[1] = b0.y; bb0[2] = b0.z; bb0[3] = b0.w;
        bb0[4] = b1.x; bb0[5] = b1.y; bb0[6] = b1.z; bb0[7] = b1.w;
    }
    int b0idx = (int)(r0 / 62500);
    float s0 = 0.f, q0 = 0.f, s1 = 0.f, q1 = 0.f;
    #pragma unroll
    for (int i = 0; i < 8; ++i) {
        long row = r0 + ty * 8 + i;
        if (row >= NCOL) continue;
        float c[8];
        #pragma unroll
        for (int j = 0; j < 4; ++j) un2(acc[i][j], c[2 * j], c[2 * j + 1]);
        float rs = 0.f, rq = 0.f;
        #pragma unroll
        for (int j = 0; j < 8; ++j) {
            float v = c[j] + bb0[j];
            c[j] = v;
            rs += v; rq += v * v;
        }
        if ((int)(row / 62500) == b0idx) { s0 += rs; q0 += rq; }
        else                             { s1 += rs; q1 += rq; }
        float4 v0 = {c[0], c[1], c[2], c[3]};
        float4 v1 = {c[4], c[5], c[6], c[7]};
        float* cp = C + row * 128 + tx * 8;
        *(float4*)(cp) = v0;
        *(float4*)(cp + 4) = v1;
    }
    #pragma unroll
    for (int off = 16; off; off >>= 1) {
        s0 += __shfl_down_sync(0xffffffffu, s0, off);
        q0 += __shfl_down_sync(0xffffffffu, q0, off);
        s1 += __shfl_down_sync(0xffffffffu, s1, off);
        q1 += __shfl_down_sync(0xffffffffu, q1, off);
    }
    __shared__ float red[8][4];
    int lane = tid & 31, w = tid >> 5;
    if (lane == 0) { red[w][0] = s0; red[w][1] = q0; red[w][2] = s1; red[w][3] = q1; }
    __syncthreads();
    if (tid == 0) {
        float ts0 = 0.f, tq0 = 0.f, ts1 = 0.f, tq1 = 0.f;
        #pragma unroll
        for (int j = 0; j < 8; ++j) {
            ts0 += red[j][0]; tq0 += red[j][1];
            ts1 += red[j][2]; tq1 += red[j][3];
        }
        atomicAdd(&g_stats[2 * b0idx],     (double)ts0);
        atomicAdd(&g_stats[2 * b0idx + 1], (double)tq0);
        if (b0idx < 3) {
            atomicAdd(&g_stats[2 * b0idx + 2], (double)ts1);
            atomicAdd(&g_stats[2 * b0idx + 3], (double)tq1);
        }
    }
}

// ---------------------------------------------------------------------------
__global__ void zero_stats() {
    if (threadIdx.x < 8) g_stats[threadIdx.x] = 0.0;
}

// Per-batch mu/inv computed ONCE (fp64), stored as float.
__global__ void finalize_stats() {
    int b = threadIdx.x;
    if (b < 4) {
        double mu  = g_stats[2 * b] / (double)PERB;
        double var = g_stats[2 * b + 1] / (double)PERB - mu * mu;
        g_mu[b]  = (float)mu;
        g_inv[b] = (float)(1.0 / sqrt(var + 1e-8));
    }
}

// intra: fused transpose + groupnorm + residual + inter-u emit (float-only math).
__global__ void trans_norm_intra(const float* __restrict__ gg, const float* __restrict__ gb,
                                 const float* __restrict__ x, float* __restrict__ out) {
    __shared__ float tile[32][33];
    int bn = blockIdx.y;
    int b = bn >> 7, n = bn & 127;
    int tk = blockIdx.x & 7, ts = blockIdx.x >> 3;
    int s = ts * 32 + threadIdx.y;
    int k = tk * 32 + threadIdx.x;
    if (s < 250 && k < 250)
        tile[threadIdx.y][threadIdx.x] =
            g_buf1[((long)(b * 250 + s)) * 32000 + n * 250 + k];
    __syncthreads();
    int k2 = tk * 32 + threadIdx.y;
    int s2 = ts * 32 + threadIdx.x;
    if (k2 < 250 && s2 < 250) {
        float mu = g_mu[b], inv = g_inv[b];
        long oi = (((long)(b * 128 + n)) * 250 + k2) * 250 + s2;
        float val = (tile[threadIdx.x][threadIdx.y] - mu) * inv * gg[n] + gb[n] + x[oi];
        out[oi] = val;
        g_buf0[(((long)(b * 250 + k2)) * 128 + n) * 250 + s2] = val;
    }
}

// inter: out[i] += gn(Lf[(b*250+k)*32000 + n*250 + s])  (float-only math)
__global__ void norm_final(const float* __restrict__ gg, const float* __restrict__ gb,
                           float* __restrict__ out) {
    int i = blockIdx.x * 256 + threadIdx.x;
    int s = i % 250;
    int t = i / 250;
    int k = t % 250; t /= 250;
    int n = t & 127;
    int b = t >> 7;
    float mu = g_mu[b], inv = g_inv[b];
    float v = g_buf1[((long)(b * 250 + k)) * 32000 + n * 250 + s];
    out[i] = (v - mu) * inv * gg[n] + gb[n] + out[i];
}

// ---------------------------------------------------------------------------
extern "C" void kernel_launch(void* const* d_in, const int* in_sizes, int n_in,
                              void* d_out, int out_size) {
    const float* x = (const float*)d_in[0];
    const float* ip[12];
    const float* pp[12];
    for (int j = 0; j < 12; ++j) ip[j] = (const float*)d_in[1 + j];
    for (int j = 0; j < 12; ++j) pp[j] = (const float*)d_in[13 + j];
    float* out = (float*)d_out;

    const int EB = TOT / 256;
    const int SMEM_OW = (64 * PITCH + 128 * PITCH) * sizeof(float);  // ~99KB
    cudaFuncSetAttribute(gemm_ow_glu, cudaFuncAttributeMaxDynamicSharedMemorySize, SMEM_OW);

    // ---- intra path ----
    pack_intra<<<dim3(64, 512), dim3(32, 32)>>>(x);
    kern_compute<<<NC, 256>>>(ip[0], ip[1], ip[2], ip[3], ip[4]);
    conv_gemm<<<dim3(16, 128), 256>>>(ip[5]);
    gemm_ow_glu<<<1954, 256, SMEM_OW>>>(ip[6], ip[7]);
    zero_stats<<<1, 32>>>();
    gemm_lw<<<1954, 256>>>(ip[8], ip[9]);
    finalize_stats<<<1, 32>>>();
    trans_norm_intra<<<dim3(64, 512), dim3(32, 32)>>>(ip[10], ip[11], x, out);

    // ---- inter path ----
    kern_compute<<<NC, 256>>>(pp[0], pp[1], pp[2], pp[3], pp[4]);
    conv_gemm<<<dim3(16, 128), 256>>>(pp[5]);
    gemm_ow_glu<<<1954, 256, SMEM_OW>>>(pp[6], pp[7]);
    zero_stats<<<1, 32>>>();
    gemm_lw<<<1954, 256>>>(pp[8], pp[9]);
    finalize_stats<<<1, 32>>>();
    norm_final<<<EB, 256>>>(pp[10], pp[11], out);
}

// round 9
// speedup vs baseline: 3.0309x; 1.0600x over previous
#include <cuda_runtime.h>
#include <cuda_bf16.h>
#include <math.h>

#define NC    128
#define LL    250
#define MM    32
#define NCOL  250000
#define TOT   32000000
#define PERB  8000000
#define PITCH 132

// Scratch
__device__ float g_buf0[32000000];  // u (packed) -> G (glu out, flat) -> u_inter
__device__ float g_buf1[32000000];  // yT -> Lf (lw out, flat)
__device__ float g_kern[NC * LL];
__device__ double g_stats[8];
__device__ float g_mu[4], g_inv[4];
// ow pre-converted to bf16 A3 = [Ah | Ah | Al], row-major 256 x 384 (u32-packed pairs)
__device__ unsigned g_owA[256 * 192];

// ---------------------------------------------------------------------------
typedef unsigned long long u64;
__device__ __forceinline__ u64 dup2(float x) {
    u64 r; asm("mov.b64 %0,{%1,%1};" : "=l"(r) : "f"(x)); return r;
}
__device__ __forceinline__ u64 pk2(float x, float y) {
    u64 r; asm("mov.b64 %0,{%1,%2};" : "=l"(r) : "f"(x), "f"(y)); return r;
}
__device__ __forceinline__ void fma2(u64& a, u64 b, u64 c) {
    asm("fma.rn.f32x2 %0,%1,%2,%0;" : "+l"(a) : "l"(b), "l"(c));
}
__device__ __forceinline__ void un2(u64 v, float& x, float& y) {
    asm("mov.b64 {%0,%1},%2;" : "=f"(x), "=f"(y) : "l"(v));
}
__device__ __forceinline__ void mma16816(float& c0, float& c1, float& c2, float& c3,
                                         unsigned a0, unsigned a1, unsigned a2, unsigned a3,
                                         unsigned b0, unsigned b1) {
    asm volatile(
        "mma.sync.aligned.m16n8k16.row.col.f32.bf16.bf16.f32 "
        "{%0,%1,%2,%3}, {%4,%5,%6,%7}, {%8,%9}, {%0,%1,%2,%3};"
        : "+f"(c0), "+f"(c1), "+f"(c2), "+f"(c3)
        : "r"(a0), "r"(a1), "r"(a2), "r"(a3), "r"(b0), "r"(b1));
}

// ---------------------------------------------------------------------------
__global__ void pack_intra(const float* __restrict__ x) {
    __shared__ float tile[32][33];
    int bh = blockIdx.y;
    int b = bh >> 7, h = bh & 127;
    int tk = blockIdx.x & 7;
    int ts = blockIdx.x >> 3;
    int k = tk * 32 + threadIdx.y;
    int s = ts * 32 + threadIdx.x;
    if (k < 250 && s < 250)
        tile[threadIdx.y][threadIdx.x] = x[(((long)bh * 250 + k) * 250) + s];
    __syncthreads();
    int s2 = ts * 32 + threadIdx.y;
    int k2 = tk * 32 + threadIdx.x;
    if (s2 < 250 && k2 < 250)
        g_buf0[(((long)(b * 250 + s2) * 128 + h) * 250) + k2] = tile[threadIdx.x][threadIdx.y];
}

// ---------------------------------------------------------------------------
__global__ void kern_compute(const float* __restrict__ log_dt,
                             const float* __restrict__ logA_re,
                             const float* __restrict__ A_im,
                             const float* __restrict__ C_re,
                             const float* __restrict__ C_im) {
    __shared__ float sCr[MM], sCi[MM], sar[MM], sai[MM];
    int h = blockIdx.x;
    int t = threadIdx.x;
    if (t < MM) {
        float dt  = expf(log_dt[h]);
        float Are = -expf(logA_re[h * MM + t]);
        float Aim = A_im[h * MM + t];
        float ar = dt * Are, ai = dt * Aim;
        float ea = expf(ar);
        float sb, cb; sincosf(ai, &sb, &cb);
        float er = ea * cb - 1.f, ei = ea * sb;
        float den = Are * Are + Aim * Aim;
        float qr = (er * Are + ei * Aim) / den;
        float qi = (ei * Are - er * Aim) / den;
        float cr = C_re[h * MM + t], ci = C_im[h * MM + t];
        sCr[t] = cr * qr - ci * qi;
        sCi[t] = cr * qi + ci * qr;
        sar[t] = ar; sai[t] = ai;
    }
    __syncthreads();
    if (t < LL) {
        float fl = (float)t;
        float sum = 0.f;
        #pragma unroll
        for (int m = 0; m < MM; ++m) {
            float ea = expf(sar[m] * fl);
            float sb, cb; sincosf(sai[m] * fl, &sb, &cb);
            sum += ea * (sCr[m] * cb - sCi[m] * sb);
        }
        g_kern[h * LL + t] = 2.f * sum;
    }
}

// ---------------------------------------------------------------------------
// Conv as per-h Toeplitz GEMM + D*u + GELU (unchanged, f32x2 CUDA cores).
__global__ void __launch_bounds__(256, 2)
conv_gemm(const float* __restrict__ D) {
    __shared__ float As[32 * PITCH];
    __shared__ float Bs[32 * PITCH];
    __shared__ float skp[512];
    int tid = threadIdx.x;
    int h = blockIdx.y;
    int rowblk = blockIdx.x >> 1, colblk = blockIdx.x & 1;
    int r0 = rowblk * 128;
    int t0 = colblk * 128;
    int nkt = colblk ? 8 : 4;

    skp[tid] = 0.f;
    skp[256 + tid] = (tid < 250) ? g_kern[h * 250 + tid] : 0.f;
    __syncthreads();

    int tx = tid & 15, ty = tid >> 4;
    u64 acc[8][4];
    #pragma unroll
    for (int i = 0; i < 8; ++i)
        #pragma unroll
        for (int j = 0; j < 4; ++j) acc[i][j] = 0ull;

    for (int kt = 0; kt < nkt; ++kt) {
        int m0 = kt * 32;
        {
            int c4 = (tid & 7) * 4;
            int rb = tid >> 3;
            #pragma unroll
            for (int p = 0; p < 4; ++p) {
                int r = rb + p * 32;
                int bb = r0 + r; if (bb > 999) bb = 999;
                const float* up = g_buf0 + ((long)bb * 128 + h) * 250 + m0 + c4;
                float2 v0 = (m0 + c4     < 250) ? *(const float2*)(up)     : make_float2(0.f, 0.f);
                float2 v1 = (m0 + c4 + 2 < 250) ? *(const float2*)(up + 2) : make_float2(0.f, 0.f);
                As[(c4 + 0) * PITCH + r] = v0.x; As[(c4 + 1) * PITCH + r] = v0.y;
                As[(c4 + 2) * PITCH + r] = v1.x; As[(c4 + 3) * PITCH + r] = v1.y;
            }
        }
        {
            int mm = tid >> 3;
            int ttb = (tid & 7) * 16;
            int base = 256 + t0 - m0 - mm + ttb;
            #pragma unroll
            for (int q = 0; q < 16; ++q)
                Bs[mm * PITCH + ttb + q] = skp[base + q];
        }
        __syncthreads();
        #pragma unroll
        for (int kk = 0; kk < 32; ++kk) {
            float4 a0 = *(const float4*)&As[kk * PITCH + ty * 8];
            float4 a1 = *(const float4*)&As[kk * PITCH + ty * 8 + 4];
            float4 b0 = *(const float4*)&Bs[kk * PITCH + tx * 8];
            float4 b1 = *(const float4*)&Bs[kk * PITCH + tx * 8 + 4];
            u64 ad[8] = {dup2(a0.x), dup2(a0.y), dup2(a0.z), dup2(a0.w),
                         dup2(a1.x), dup2(a1.y), dup2(a1.z), dup2(a1.w)};
            u64 bp4[4] = {pk2(b0.x, b0.y), pk2(b0.z, b0.w),
                          pk2(b1.x, b1.y), pk2(b1.z, b1.w)};
            #pragma unroll
            for (int i = 0; i < 8; ++i)
                #pragma unroll
                for (int j = 0; j < 4; ++j)
                    fma2(acc[i][j], ad[i], bp4[j]);
        }
        __syncthreads();
    }

    float dh = D[h];
    #pragma unroll
    for (int i = 0; i < 8; ++i) {
        int bb = r0 + ty * 8 + i;
        if (bb > 999) continue;
        float c[8];
        #pragma unroll
        for (int j = 0; j < 4; ++j) un2(acc[i][j], c[2 * j], c[2 * j + 1]);
        int tbase = t0 + tx * 8;
        const float* up = g_buf0 + ((long)bb * 128 + h) * 250 + tbase;
        float* yp = g_buf1 + (long)h * NCOL + (long)bb * 250 + tbase;
        #pragma unroll
        for (int j2 = 0; j2 < 4; ++j2) {
            int t = tbase + 2 * j2;
            if (t < 250) {
                float2 uv = *(const float2*)(up + 2 * j2);
                float y0 = c[2 * j2]     + dh * uv.x;
                float y1 = c[2 * j2 + 1] + dh * uv.y;
                float e0 = y0 + 0.044715f * y0 * y0 * y0;
                float e1 = y1 + 0.044715f * y1 * y1 * y1;
                float2 g;
                g.x = 0.5f * y0 * (1.f + tanhf(0.7978845608f * e0));
                g.y = 0.5f * y1 * (1.f + tanhf(0.7978845608f * e1));
                *(float2*)(yp + 2 * j2) = g;
            }
        }
    }
}

// ---------------------------------------------------------------------------
// Pre-convert ow (256x128 fp32) -> A3 bf16 [256][384]: [Ah | Ah | Al], u32 pairs.
__global__ void conv_ow_bf16(const float* __restrict__ ow) {
    int idx = blockIdx.x * 256 + threadIdx.x;   // 16384 pairs
    int o = idx >> 6, kp = idx & 63;            // kp: pair index (k = 2*kp)
    float v0 = ow[o * 128 + kp * 2];
    float v1 = ow[o * 128 + kp * 2 + 1];
    __nv_bfloat16 h0 = __float2bfloat16(v0);
    __nv_bfloat16 h1 = __float2bfloat16(v1);
    __nv_bfloat16 l0 = __float2bfloat16(v0 - __bfloat162float(h0));
    __nv_bfloat16 l1 = __float2bfloat16(v1 - __bfloat162float(h1));
    unsigned hp, lp;
    asm("mov.b32 %0, {%1, %2};" : "=r"(hp) : "h"(*(unsigned short*)&h0), "h"(*(unsigned short*)&h1));
    asm("mov.b32 %0, {%1, %2};" : "=r"(lp) : "h"(*(unsigned short*)&l0), "h"(*(unsigned short*)&l1));
    g_owA[o * 192 + kp]       = hp;   // Ah
    g_owA[o * 192 + 64 + kp]  = hp;   // Ah (again)
    g_owA[o * 192 + 128 + kp] = lp;   // Al
}

// ---------------------------------------------------------------------------
// mma.sync bf16 2-split fused ow GEMM + GLU.
// z[256 x 64cols] = A3[256x384] @ B3[384 x 64], B3 = [Bh; Bl; Bh] from yT tile.
// Block: 256 thr (8 warps, 4m x 2n), warp tile 64x32, K=384 (24 k-steps).
// Epilogue: GLU(z1, z2) -> G float2 stores.
// Dyn smem (bytes): Bs bf16[64][392] @0 (50176) | Ach u32[256][18] @50176 (18432)
//                   | stash f32[128][66] @68608 (33792) | sbias f32[256] @102400 (1024)
__global__ void __launch_bounds__(256)
gemm_ow_mma(const float* __restrict__ bias) {
    extern __shared__ char dsm[];
    __nv_bfloat16* Bs16 = (__nv_bfloat16*)dsm;          // [c][392]
    unsigned* Bsu = (unsigned*)dsm;                      // u32 view (stride 196)
    unsigned* Ach = (unsigned*)(dsm + 50176);            // [o][18]
    float* stash = (float*)(dsm + 68608);                // [o2][66]
    float* sbias = (float*)(dsm + 102400);

    int tid = threadIdx.x;
    int w = tid >> 5, lane = tid & 31;
    int g = lane >> 2, tg = lane & 3;
    int mw = w >> 1, nw = w & 1;
    long n0 = (long)blockIdx.x * 64;

    sbias[tid] = bias[tid];

    // Build B3 in smem from yT (g_buf1): hi at k, lo at k+128, hi at k+256.
    for (int i = tid; i < 128 * 64; i += 256) {
        int hk = i >> 6, c = i & 63;
        long col = n0 + c; if (col >= NCOL) col = NCOL - 1;
        float v = g_buf1[(long)hk * NCOL + col];
        __nv_bfloat16 hi = __float2bfloat16(v);
        __nv_bfloat16 lo = __float2bfloat16(v - __bfloat162float(hi));
        __nv_bfloat16* bp = Bs16 + c * 392;
        bp[hk] = hi; bp[hk + 128] = lo; bp[hk + 256] = hi;
    }

    float acc[4][4][4];
    #pragma unroll
    for (int i = 0; i < 4; ++i)
        #pragma unroll
        for (int j = 0; j < 4; ++j)
            #pragma unroll
            for (int q = 0; q < 4; ++q) acc[i][j][q] = 0.f;

    for (int kc = 0; kc < 12; ++kc) {
        // Load A chunk: 256 rows x 16 u32 (32 bf16 k) from g_owA
        __syncthreads();
        #pragma unroll
        for (int p = 0; p < 16; ++p) {
            int i = tid + p * 256;            // 4096 u32
            int o = i >> 4, kk = i & 15;
            Ach[o * 18 + kk] = g_owA[o * 192 + kc * 16 + kk];
        }
        __syncthreads();
        #pragma unroll
        for (int s = 0; s < 2; ++s) {
            int ks = kc * 2 + s;
            // B fragments for 4 n-tiles
            unsigned bf0[4], bf1[4];
            #pragma unroll
            for (int j = 0; j < 4; ++j) {
                int c = nw * 32 + j * 8 + g;
                bf0[j] = Bsu[c * 196 + ks * 8 + tg];
                bf1[j] = Bsu[c * 196 + ks * 8 + tg + 4];
            }
            #pragma unroll
            for (int i = 0; i < 4; ++i) {
                int r0 = mw * 64 + i * 16 + g;
                int base0 = r0 * 18 + s * 8 + tg;
                int base1 = (r0 + 8) * 18 + s * 8 + tg;
                unsigned a0 = Ach[base0], a1 = Ach[base1];
                unsigned a2 = Ach[base0 + 4], a3 = Ach[base1 + 4];
                #pragma unroll
                for (int j = 0; j < 4; ++j)
                    mma16816(acc[i][j][0], acc[i][j][1], acc[i][j][2], acc[i][j][3],
                             a0, a1, a2, a3, bf0[j], bf1[j]);
            }
        }
    }
    __syncthreads();

    // Warps 4-7 (rows 128..255 = z2): stash z2 + bias
    if (w >= 4) {
        #pragma unroll
        for (int i = 0; i < 4; ++i) {
            int m = mw * 64 + i * 16 + g;          // 128..255
            int o2a = m - 128, o2b = m - 120;      // rows g and g+8
            float ba = sbias[128 + o2a], bb2 = sbias[128 + o2b];
            #pragma unroll
            for (int j = 0; j < 4; ++j) {
                int cl = nw * 32 + j * 8 + tg * 2;
                stash[o2a * 66 + cl]     = acc[i][j][0] + ba;
                stash[o2a * 66 + cl + 1] = acc[i][j][1] + ba;
                stash[o2b * 66 + cl]     = acc[i][j][2] + bb2;
                stash[o2b * 66 + cl + 1] = acc[i][j][3] + bb2;
            }
        }
    }
    __syncthreads();

    // Warps 0-3 (rows 0..127 = z1): GLU + store G
    if (w < 4) {
        #pragma unroll
        for (int i = 0; i < 4; ++i) {
            int oa = mw * 64 + i * 16 + g;
            int ob = oa + 8;
            float ba = sbias[oa], bb2 = sbias[ob];
            #pragma unroll
            for (int j = 0; j < 4; ++j) {
                int cl = nw * 32 + j * 8 + tg * 2;
                long col = n0 + cl;
                if (col < NCOL) {
                    int bb = (int)(col / 250);
                    int l  = (int)(col - (long)bb * 250);
                    float z1a = acc[i][j][0] + ba;
                    float z1b = acc[i][j][1] + ba;
                    float z2a = stash[oa * 66 + cl];
                    float z2b = stash[oa * 66 + cl + 1];
                    float2 gv;
                    gv.x = z1a / (1.f + expf(-z2a));
                    gv.y = z1b / (1.f + expf(-z2b));
                    *(float2*)&g_buf0[((long)bb * 128 + oa) * 250 + l] = gv;
                    float z3a = acc[i][j][2] + bb2;
                    float z3b = acc[i][j][3] + bb2;
                    float z4a = stash[ob * 66 + cl];
                    float z4b = stash[ob * 66 + cl + 1];
                    float2 gw;
                    gw.x = z3a / (1.f + expf(-z4a));
                    gw.y = z3b / (1.f + expf(-z4b));
                    *(float2*)&g_buf0[((long)bb * 128 + ob) * 250 + l] = gw;
                }
            }
        }
    }
}

// ---------------------------------------------------------------------------
// GEMM2 (lw) + fused groupnorm stats (unchanged).
__global__ void __launch_bounds__(256, 2)
gemm_lw(const float* __restrict__ W, const float* __restrict__ bias) {
    const float* __restrict__ G = g_buf0;
    float* __restrict__ C = g_buf1;
    __shared__ float Gs[32 * PITCH];
    __shared__ float Ws[32 * PITCH];

    int tid = threadIdx.x;
    int tx = tid & 15, ty = tid >> 4;
    long r0 = (long)blockIdx.x * 128;

    u64 acc[8][4];
    #pragma unroll
    for (int i = 0; i < 8; ++i)
        #pragma unroll
        for (int j = 0; j < 4; ++j) acc[i][j] = 0ull;

    for (int kc = 0; kc < 4; ++kc) {
        int c4 = (tid & 7) * 4;
        int rb = tid >> 3;
        #pragma unroll
        for (int p = 0; p < 4; ++p) {
            int r = rb + p * 32;
            long grow = r0 + r;
            if (grow >= NCOL) grow = NCOL - 1;
            float4 v = *(const float4*)(G + grow * 128 + kc * 32 + c4);
            Gs[(c4 + 0) * PITCH + r] = v.x; Gs[(c4 + 1) * PITCH + r] = v.y;
            Gs[(c4 + 2) * PITCH + r] = v.z; Gs[(c4 + 3) * PITCH + r] = v.w;
            float4 wv = *(const float4*)(W + (long)r * 128 + kc * 32 + c4);
            Ws[(c4 + 0) * PITCH + r] = wv.x; Ws[(c4 + 1) * PITCH + r] = wv.y;
            Ws[(c4 + 2) * PITCH + r] = wv.z; Ws[(c4 + 3) * PITCH + r] = wv.w;
        }
        __syncthreads();
        #pragma unroll
        for (int kk = 0; kk < 32; ++kk) {
            float4 a0 = *(const float4*)&Gs[kk * PITCH + ty * 8];
            float4 a1 = *(const float4*)&Gs[kk * PITCH + ty * 8 + 4];
            float4 b0 = *(const float4*)&Ws[kk * PITCH + tx * 8];
            float4 b1 = *(const float4*)&Ws[kk * PITCH + tx * 8 + 4];
            u64 ad[8] = {dup2(a0.x), dup2(a0.y), dup2(a0.z), dup2(a0.w),
                         dup2(a1.x), dup2(a1.y), dup2(a1.z), dup2(a1.w)};
            u64 bp4[4] = {pk2(b0.x, b0.y), pk2(b0.z, b0.w),
                          pk2(b1.x, b1.y), pk2(b1.z, b1.w)};
            #pragma unroll
            for (int i = 0; i < 8; ++i)
                #pragma unroll
                for (int j = 0; j < 4; ++j)
                    fma2(acc[i][j], ad[i], bp4[j]);
        }
        __syncthreads();
    }
    float bb0[8];
    {
        float4 b0 = *(const float4*)(bias + tx * 8);
        float4 b1 = *(const float4*)(bias + tx * 8 + 4);
        bb0[0] = b0.x; bb0[1] = b0.y; bb0[2] = b0.z; bb0[3] = b0.w;
        bb0[4] = b1.x; bb0[5] = b1.y; bb0[6] = b1.z; bb0[7] = b1.w;
    }
    int b0idx = (int)(r0 / 62500);
    float s0 = 0.f, q0 = 0.f, s1 = 0.f, q1 = 0.f;
    #pragma unroll
    for (int i = 0; i < 8; ++i) {
        long row = r0 + ty * 8 + i;
        if (row >= NCOL) continue;
        float c[8];
        #pragma unroll
        for (int j = 0; j < 4; ++j) un2(acc[i][j], c[2 * j], c[2 * j + 1]);
        float rs = 0.f, rq = 0.f;
        #pragma unroll
        for (int j = 0; j < 8; ++j) {
            float v = c[j] + bb0[j];
            c[j] = v;
            rs += v; rq += v * v;
        }
        if ((int)(row / 62500) == b0idx) { s0 += rs; q0 += rq; }
        else                             { s1 += rs; q1 += rq; }
        float4 v0 = {c[0], c[1], c[2], c[3]};
        float4 v1 = {c[4], c[5], c[6], c[7]};
        float* cp = C + row * 128 + tx * 8;
        *(float4*)(cp) = v0;
        *(float4*)(cp + 4) = v1;
    }
    #pragma unroll
    for (int off = 16; off; off >>= 1) {
        s0 += __shfl_down_sync(0xffffffffu, s0, off);
        q0 += __shfl_down_sync(0xffffffffu, q0, off);
        s1 += __shfl_down_sync(0xffffffffu, s1, off);
        q1 += __shfl_down_sync(0xffffffffu, q1, off);
    }
    __shared__ float red[8][4];
    int lane = tid & 31, w = tid >> 5;
    if (lane == 0) { red[w][0] = s0; red[w][1] = q0; red[w][2] = s1; red[w][3] = q1; }
    __syncthreads();
    if (tid == 0) {
        float ts0 = 0.f, tq0 = 0.f, ts1 = 0.f, tq1 = 0.f;
        #pragma unroll
        for (int j = 0; j < 8; ++j) {
            ts0 += red[j][0]; tq0 += red[j][1];
            ts1 += red[j][2]; tq1 += red[j][3];
        }
        atomicAdd(&g_stats[2 * b0idx],     (double)ts0);
        atomicAdd(&g_stats[2 * b0idx + 1], (double)tq0);
        if (b0idx < 3) {
            atomicAdd(&g_stats[2 * b0idx + 2], (double)ts1);
            atomicAdd(&g_stats[2 * b0idx + 3], (double)tq1);
        }
    }
}

// ---------------------------------------------------------------------------
__global__ void zero_stats() {
    if (threadIdx.x < 8) g_stats[threadIdx.x] = 0.0;
}

__global__ void finalize_stats() {
    int b = threadIdx.x;
    if (b < 4) {
        double mu  = g_stats[2 * b] / (double)PERB;
        double var = g_stats[2 * b + 1] / (double)PERB - mu * mu;
        g_mu[b]  = (float)mu;
        g_inv[b] = (float)(1.0 / sqrt(var + 1e-8));
    }
}

__global__ void trans_norm_intra(const float* __restrict__ gg, const float* __restrict__ gb,
                                 const float* __restrict__ x, float* __restrict__ out) {
    __shared__ float tile[32][33];
    int bn = blockIdx.y;
    int b = bn >> 7, n = bn & 127;
    int tk = blockIdx.x & 7, ts = blockIdx.x >> 3;
    int s = ts * 32 + threadIdx.y;
    int k = tk * 32 + threadIdx.x;
    if (s < 250 && k < 250)
        tile[threadIdx.y][threadIdx.x] =
            g_buf1[((long)(b * 250 + s)) * 32000 + n * 250 + k];
    __syncthreads();
    int k2 = tk * 32 + threadIdx.y;
    int s2 = ts * 32 + threadIdx.x;
    if (k2 < 250 && s2 < 250) {
        float mu = g_mu[b], inv = g_inv[b];
        long oi = (((long)(b * 128 + n)) * 250 + k2) * 250 + s2;
        float val = (tile[threadIdx.x][threadIdx.y] - mu) * inv * gg[n] + gb[n] + x[oi];
        out[oi] = val;
        g_buf0[(((long)(b * 250 + k2)) * 128 + n) * 250 + s2] = val;
    }
}

__global__ void norm_final(const float* __restrict__ gg, const float* __restrict__ gb,
                           float* __restrict__ out) {
    int i = blockIdx.x * 256 + threadIdx.x;
    int s = i % 250;
    int t = i / 250;
    int k = t % 250; t /= 250;
    int n = t & 127;
    int b = t >> 7;
    float mu = g_mu[b], inv = g_inv[b];
    float v = g_buf1[((long)(b * 250 + k)) * 32000 + n * 250 + s];
    out[i] = (v - mu) * inv * gg[n] + gb[n] + out[i];
}

// ---------------------------------------------------------------------------
extern "C" void kernel_launch(void* const* d_in, const int* in_sizes, int n_in,
                              void* d_out, int out_size) {
    const float* x = (const float*)d_in[0];
    const float* ip[12];
    const float* pp[12];
    for (int j = 0; j < 12; ++j) ip[j] = (const float*)d_in[1 + j];
    for (int j = 0; j < 12; ++j) pp[j] = (const float*)d_in[13 + j];
    float* out = (float*)d_out;

    const int EB = TOT / 256;
    const int SMEM_MMA = 103424;
    cudaFuncSetAttribute(gemm_ow_mma, cudaFuncAttributeMaxDynamicSharedMemorySize, SMEM_MMA);
    const int GOW = (NCOL + 63) / 64;   // 3907

    // ---- intra path ----
    pack_intra<<<dim3(64, 512), dim3(32, 32)>>>(x);
    kern_compute<<<NC, 256>>>(ip[0], ip[1], ip[2], ip[3], ip[4]);
    conv_gemm<<<dim3(16, 128), 256>>>(ip[5]);
    conv_ow_bf16<<<64, 256>>>(ip[6]);
    gemm_ow_mma<<<GOW, 256, SMEM_MMA>>>(ip[7]);
    zero_stats<<<1, 32>>>();
    gemm_lw<<<1954, 256>>>(ip[8], ip[9]);
    finalize_stats<<<1, 32>>>();
    trans_norm_intra<<<dim3(64, 512), dim3(32, 32)>>>(ip[10], ip[11], x, out);

    // ---- inter path ----
    kern_compute<<<NC, 256>>>(pp[0], pp[1], pp[2], pp[3], pp[4]);
    conv_gemm<<<dim3(16, 128), 256>>>(pp[5]);
    conv_ow_bf16<<<64, 256>>>(pp[6]);
    gemm_ow_mma<<<GOW, 256, SMEM_MMA>>>(pp[7]);
    zero_stats<<<1, 32>>>();
    gemm_lw<<<1954, 256>>>(pp[8], pp[9]);
    finalize_stats<<<1, 32>>>();
    norm_final<<<EB, 256>>>(pp[10], pp[11], out);
}

// round 10
// speedup vs baseline: 3.0403x; 1.0031x over previous
#include <cuda_runtime.h>
#include <cuda_bf16.h>
#include <math.h>

#define NC    128
#define LL    250
#define MM    32
#define NCOL  250000
#define TOT   32000000
#define PERB  8000000
#define PITCH 132

// Scratch
__device__ float g_buf0[32000000];  // u (packed) -> G (glu out, flat) -> u_inter
__device__ float g_buf1[32000000];  // yT -> Lf (lw out, flat)
__device__ float g_kern[NC * LL];
__device__ double g_stats[8];
__device__ float g_mu[4], g_inv[4];
// ow pre-converted to bf16 A3 = [Ah | Ah | Al], row-major 256 x 384 (u32-packed pairs)
__device__ unsigned g_owA[256 * 192];
// lw pre-converted to bf16 B3 = [Wh | Wl | Wh], per-col k-contiguous 128 x 384
__device__ unsigned g_lwB[128 * 192];

// ---------------------------------------------------------------------------
typedef unsigned long long u64;
__device__ __forceinline__ u64 dup2(float x) {
    u64 r; asm("mov.b64 %0,{%1,%1};" : "=l"(r) : "f"(x)); return r;
}
__device__ __forceinline__ u64 pk2(float x, float y) {
    u64 r; asm("mov.b64 %0,{%1,%2};" : "=l"(r) : "f"(x), "f"(y)); return r;
}
__device__ __forceinline__ void fma2(u64& a, u64 b, u64 c) {
    asm("fma.rn.f32x2 %0,%1,%2,%0;" : "+l"(a) : "l"(b), "l"(c));
}
__device__ __forceinline__ void un2(u64 v, float& x, float& y) {
    asm("mov.b64 {%0,%1},%2;" : "=f"(x), "=f"(y) : "l"(v));
}
__device__ __forceinline__ void mma16816(float& c0, float& c1, float& c2, float& c3,
                                         unsigned a0, unsigned a1, unsigned a2, unsigned a3,
                                         unsigned b0, unsigned b1) {
    asm volatile(
        "mma.sync.aligned.m16n8k16.row.col.f32.bf16.bf16.f32 "
        "{%0,%1,%2,%3}, {%4,%5,%6,%7}, {%8,%9}, {%0,%1,%2,%3};"
        : "+f"(c0), "+f"(c1), "+f"(c2), "+f"(c3)
        : "r"(a0), "r"(a1), "r"(a2), "r"(a3), "r"(b0), "r"(b1));
}
__device__ __forceinline__ unsigned pkbf(__nv_bfloat16 a, __nv_bfloat16 b) {
    unsigned r;
    asm("mov.b32 %0, {%1, %2};" : "=r"(r)
        : "h"(*(unsigned short*)&a), "h"(*(unsigned short*)&b));
    return r;
}

// ---------------------------------------------------------------------------
__global__ void pack_intra(const float* __restrict__ x) {
    __shared__ float tile[32][33];
    int bh = blockIdx.y;
    int b = bh >> 7, h = bh & 127;
    int tk = blockIdx.x & 7;
    int ts = blockIdx.x >> 3;
    int k = tk * 32 + threadIdx.y;
    int s = ts * 32 + threadIdx.x;
    if (k < 250 && s < 250)
        tile[threadIdx.y][threadIdx.x] = x[(((long)bh * 250 + k) * 250) + s];
    __syncthreads();
    int s2 = ts * 32 + threadIdx.y;
    int k2 = tk * 32 + threadIdx.x;
    if (s2 < 250 && k2 < 250)
        g_buf0[(((long)(b * 250 + s2) * 128 + h) * 250) + k2] = tile[threadIdx.x][threadIdx.y];
}

// ---------------------------------------------------------------------------
__global__ void kern_compute(const float* __restrict__ log_dt,
                             const float* __restrict__ logA_re,
                             const float* __restrict__ A_im,
                             const float* __restrict__ C_re,
                             const float* __restrict__ C_im) {
    __shared__ float sCr[MM], sCi[MM], sar[MM], sai[MM];
    int h = blockIdx.x;
    int t = threadIdx.x;
    if (t < MM) {
        float dt  = expf(log_dt[h]);
        float Are = -expf(logA_re[h * MM + t]);
        float Aim = A_im[h * MM + t];
        float ar = dt * Are, ai = dt * Aim;
        float ea = expf(ar);
        float sb, cb; sincosf(ai, &sb, &cb);
        float er = ea * cb - 1.f, ei = ea * sb;
        float den = Are * Are + Aim * Aim;
        float qr = (er * Are + ei * Aim) / den;
        float qi = (ei * Are - er * Aim) / den;
        float cr = C_re[h * MM + t], ci = C_im[h * MM + t];
        sCr[t] = cr * qr - ci * qi;
        sCi[t] = cr * qi + ci * qr;
        sar[t] = ar; sai[t] = ai;
    }
    __syncthreads();
    if (t < LL) {
        float fl = (float)t;
        float sum = 0.f;
        #pragma unroll
        for (int m = 0; m < MM; ++m) {
            float ea = expf(sar[m] * fl);
            float sb, cb; sincosf(sai[m] * fl, &sb, &cb);
            sum += ea * (sCr[m] * cb - sCi[m] * sb);
        }
        g_kern[h * LL + t] = 2.f * sum;
    }
}

// ---------------------------------------------------------------------------
// Conv as per-h Toeplitz GEMM + D*u + GELU (f32x2 CUDA cores).
__global__ void __launch_bounds__(256, 2)
conv_gemm(const float* __restrict__ D) {
    __shared__ float As[32 * PITCH];
    __shared__ float Bs[32 * PITCH];
    __shared__ float skp[512];
    int tid = threadIdx.x;
    int h = blockIdx.y;
    int rowblk = blockIdx.x >> 1, colblk = blockIdx.x & 1;
    int r0 = rowblk * 128;
    int t0 = colblk * 128;
    int nkt = colblk ? 8 : 4;

    skp[tid] = 0.f;
    skp[256 + tid] = (tid < 250) ? g_kern[h * 250 + tid] : 0.f;
    __syncthreads();

    int tx = tid & 15, ty = tid >> 4;
    u64 acc[8][4];
    #pragma unroll
    for (int i = 0; i < 8; ++i)
        #pragma unroll
        for (int j = 0; j < 4; ++j) acc[i][j] = 0ull;

    for (int kt = 0; kt < nkt; ++kt) {
        int m0 = kt * 32;
        {
            int c4 = (tid & 7) * 4;
            int rb = tid >> 3;
            #pragma unroll
            for (int p = 0; p < 4; ++p) {
                int r = rb + p * 32;
                int bb = r0 + r; if (bb > 999) bb = 999;
                const float* up = g_buf0 + ((long)bb * 128 + h) * 250 + m0 + c4;
                float2 v0 = (m0 + c4     < 250) ? *(const float2*)(up)     : make_float2(0.f, 0.f);
                float2 v1 = (m0 + c4 + 2 < 250) ? *(const float2*)(up + 2) : make_float2(0.f, 0.f);
                As[(c4 + 0) * PITCH + r] = v0.x; As[(c4 + 1) * PITCH + r] = v0.y;
                As[(c4 + 2) * PITCH + r] = v1.x; As[(c4 + 3) * PITCH + r] = v1.y;
            }
        }
        {
            int mm = tid >> 3;
            int ttb = (tid & 7) * 16;
            int base = 256 + t0 - m0 - mm + ttb;
            #pragma unroll
            for (int q = 0; q < 16; ++q)
                Bs[mm * PITCH + ttb + q] = skp[base + q];
        }
        __syncthreads();
        #pragma unroll
        for (int kk = 0; kk < 32; ++kk) {
            float4 a0 = *(const float4*)&As[kk * PITCH + ty * 8];
            float4 a1 = *(const float4*)&As[kk * PITCH + ty * 8 + 4];
            float4 b0 = *(const float4*)&Bs[kk * PITCH + tx * 8];
            float4 b1 = *(const float4*)&Bs[kk * PITCH + tx * 8 + 4];
            u64 ad[8] = {dup2(a0.x), dup2(a0.y), dup2(a0.z), dup2(a0.w),
                         dup2(a1.x), dup2(a1.y), dup2(a1.z), dup2(a1.w)};
            u64 bp4[4] = {pk2(b0.x, b0.y), pk2(b0.z, b0.w),
                          pk2(b1.x, b1.y), pk2(b1.z, b1.w)};
            #pragma unroll
            for (int i = 0; i < 8; ++i)
                #pragma unroll
                for (int j = 0; j < 4; ++j)
                    fma2(acc[i][j], ad[i], bp4[j]);
        }
        __syncthreads();
    }

    float dh = D[h];
    #pragma unroll
    for (int i = 0; i < 8; ++i) {
        int bb = r0 + ty * 8 + i;
        if (bb > 999) continue;
        float c[8];
        #pragma unroll
        for (int j = 0; j < 4; ++j) un2(acc[i][j], c[2 * j], c[2 * j + 1]);
        int tbase = t0 + tx * 8;
        const float* up = g_buf0 + ((long)bb * 128 + h) * 250 + tbase;
        float* yp = g_buf1 + (long)h * NCOL + (long)bb * 250 + tbase;
        #pragma unroll
        for (int j2 = 0; j2 < 4; ++j2) {
            int t = tbase + 2 * j2;
            if (t < 250) {
                float2 uv = *(const float2*)(up + 2 * j2);
                float y0 = c[2 * j2]     + dh * uv.x;
                float y1 = c[2 * j2 + 1] + dh * uv.y;
                float e0 = y0 + 0.044715f * y0 * y0 * y0;
                float e1 = y1 + 0.044715f * y1 * y1 * y1;
                float2 g;
                g.x = 0.5f * y0 * (1.f + tanhf(0.7978845608f * e0));
                g.y = 0.5f * y1 * (1.f + tanhf(0.7978845608f * e1));
                *(float2*)(yp + 2 * j2) = g;
            }
        }
    }
}

// ---------------------------------------------------------------------------
// Pre-convert ow -> A3 [Ah | Ah | Al]  and lw -> B3 [Wh | Wl | Wh]
__global__ void conv_ow_bf16(const float* __restrict__ ow) {
    int idx = blockIdx.x * 256 + threadIdx.x;   // 16384 pairs
    int o = idx >> 6, kp = idx & 63;
    float v0 = ow[o * 128 + kp * 2];
    float v1 = ow[o * 128 + kp * 2 + 1];
    __nv_bfloat16 h0 = __float2bfloat16(v0);
    __nv_bfloat16 h1 = __float2bfloat16(v1);
    __nv_bfloat16 l0 = __float2bfloat16(v0 - __bfloat162float(h0));
    __nv_bfloat16 l1 = __float2bfloat16(v1 - __bfloat162float(h1));
    unsigned hp = pkbf(h0, h1), lp = pkbf(l0, l1);
    g_owA[o * 192 + kp]       = hp;
    g_owA[o * 192 + 64 + kp]  = hp;
    g_owA[o * 192 + 128 + kp] = lp;
}

__global__ void conv_lw_bf16(const float* __restrict__ W) {
    int idx = blockIdx.x * 256 + threadIdx.x;   // 8192 pairs
    int c = idx >> 6, kp = idx & 63;
    float v0 = W[c * 128 + kp * 2];
    float v1 = W[c * 128 + kp * 2 + 1];
    __nv_bfloat16 h0 = __float2bfloat16(v0);
    __nv_bfloat16 h1 = __float2bfloat16(v1);
    __nv_bfloat16 l0 = __float2bfloat16(v0 - __bfloat162float(h0));
    __nv_bfloat16 l1 = __float2bfloat16(v1 - __bfloat162float(h1));
    unsigned hp = pkbf(h0, h1), lp = pkbf(l0, l1);
    g_lwB[c * 192 + kp]       = hp;   // pairs with Gh
    g_lwB[c * 192 + 64 + kp]  = lp;   // pairs with Gh
    g_lwB[c * 192 + 128 + kp] = hp;   // pairs with Gl
}

// ---------------------------------------------------------------------------
// mma.sync bf16 2-split fused ow GEMM + GLU (R9, proven).
__global__ void __launch_bounds__(256)
gemm_ow_mma(const float* __restrict__ bias) {
    extern __shared__ char dsm[];
    __nv_bfloat16* Bs16 = (__nv_bfloat16*)dsm;          // [c][392]
    unsigned* Bsu = (unsigned*)dsm;                      // u32 view (stride 196)
    unsigned* Ach = (unsigned*)(dsm + 50176);            // [o][18]
    float* stash = (float*)(dsm + 68608);                // [o2][66]
    float* sbias = (float*)(dsm + 102400);

    int tid = threadIdx.x;
    int w = tid >> 5, lane = tid & 31;
    int g = lane >> 2, tg = lane & 3;
    int mw = w >> 1, nw = w & 1;
    long n0 = (long)blockIdx.x * 64;

    sbias[tid] = bias[tid];

    for (int i = tid; i < 128 * 64; i += 256) {
        int hk = i >> 6, c = i & 63;
        long col = n0 + c; if (col >= NCOL) col = NCOL - 1;
        float v = g_buf1[(long)hk * NCOL + col];
        __nv_bfloat16 hi = __float2bfloat16(v);
        __nv_bfloat16 lo = __float2bfloat16(v - __bfloat162float(hi));
        __nv_bfloat16* bp = Bs16 + c * 392;
        bp[hk] = hi; bp[hk + 128] = lo; bp[hk + 256] = hi;
    }

    float acc[4][4][4];
    #pragma unroll
    for (int i = 0; i < 4; ++i)
        #pragma unroll
        for (int j = 0; j < 4; ++j)
            #pragma unroll
            for (int q = 0; q < 4; ++q) acc[i][j][q] = 0.f;

    for (int kc = 0; kc < 12; ++kc) {
        __syncthreads();
        #pragma unroll
        for (int p = 0; p < 16; ++p) {
            int i = tid + p * 256;
            int o = i >> 4, kk = i & 15;
            Ach[o * 18 + kk] = g_owA[o * 192 + kc * 16 + kk];
        }
        __syncthreads();
        #pragma unroll
        for (int s = 0; s < 2; ++s) {
            int ks = kc * 2 + s;
            unsigned bf0[4], bf1[4];
            #pragma unroll
            for (int j = 0; j < 4; ++j) {
                int c = nw * 32 + j * 8 + g;
                bf0[j] = Bsu[c * 196 + ks * 8 + tg];
                bf1[j] = Bsu[c * 196 + ks * 8 + tg + 4];
            }
            #pragma unroll
            for (int i = 0; i < 4; ++i) {
                int r0 = mw * 64 + i * 16 + g;
                int base0 = r0 * 18 + s * 8 + tg;
                int base1 = (r0 + 8) * 18 + s * 8 + tg;
                unsigned a0 = Ach[base0], a1 = Ach[base1];
                unsigned a2 = Ach[base0 + 4], a3 = Ach[base1 + 4];
                #pragma unroll
                for (int j = 0; j < 4; ++j)
                    mma16816(acc[i][j][0], acc[i][j][1], acc[i][j][2], acc[i][j][3],
                             a0, a1, a2, a3, bf0[j], bf1[j]);
            }
        }
    }
    __syncthreads();

    if (w >= 4) {
        #pragma unroll
        for (int i = 0; i < 4; ++i) {
            int m = mw * 64 + i * 16 + g;
            int o2a = m - 128, o2b = m - 120;
            float ba = sbias[128 + o2a], bb2 = sbias[128 + o2b];
            #pragma unroll
            for (int j = 0; j < 4; ++j) {
                int cl = nw * 32 + j * 8 + tg * 2;
                stash[o2a * 66 + cl]     = acc[i][j][0] + ba;
                stash[o2a * 66 + cl + 1] = acc[i][j][1] + ba;
                stash[o2b * 66 + cl]     = acc[i][j][2] + bb2;
                stash[o2b * 66 + cl + 1] = acc[i][j][3] + bb2;
            }
        }
    }
    __syncthreads();

    if (w < 4) {
        #pragma unroll
        for (int i = 0; i < 4; ++i) {
            int oa = mw * 64 + i * 16 + g;
            int ob = oa + 8;
            float ba = sbias[oa], bb2 = sbias[ob];
            #pragma unroll
            for (int j = 0; j < 4; ++j) {
                int cl = nw * 32 + j * 8 + tg * 2;
                long col = n0 + cl;
                if (col < NCOL) {
                    int bb = (int)(col / 250);
                    int l  = (int)(col - (long)bb * 250);
                    float z1a = acc[i][j][0] + ba;
                    float z1b = acc[i][j][1] + ba;
                    float z2a = stash[oa * 66 + cl];
                    float z2b = stash[oa * 66 + cl + 1];
                    float2 gv;
                    gv.x = z1a / (1.f + expf(-z2a));
                    gv.y = z1b / (1.f + expf(-z2b));
                    *(float2*)&g_buf0[((long)bb * 128 + oa) * 250 + l] = gv;
                    float z3a = acc[i][j][2] + bb2;
                    float z3b = acc[i][j][3] + bb2;
                    float z4a = stash[ob * 66 + cl];
                    float z4b = stash[ob * 66 + cl + 1];
                    float2 gw;
                    gw.x = z3a / (1.f + expf(-z4a));
                    gw.y = z3b / (1.f + expf(-z4b));
                    *(float2*)&g_buf0[((long)bb * 128 + ob) * 250 + l] = gw;
                }
            }
        }
    }
}

// ---------------------------------------------------------------------------
// mma.sync bf16 2-split lw GEMM + fused groupnorm stats.
// C[128 rows][128 c] per block: A3 = [Gh|Gh|Gl] (chunk-converted in smem),
// B3 = g_lwB. 8 warps = 4m x 2n; warp tile 32 rows x 64 cols; 24 k-steps.
__global__ void __launch_bounds__(256)
gemm_lw_mma(const float* __restrict__ bias) {
    __shared__ unsigned Ach[128 * 18];
    __shared__ unsigned Bch[128 * 18];
    __shared__ float sbias[128];
    __shared__ float red[8][4];

    int tid = threadIdx.x;
    int w = tid >> 5, lane = tid & 31;
    int g = lane >> 2, tg = lane & 3;
    int mw = w >> 1, nw = w & 1;
    long r0 = (long)blockIdx.x * 128;

    if (tid < 128) sbias[tid] = bias[tid];

    float acc[2][8][4];
    #pragma unroll
    for (int i = 0; i < 2; ++i)
        #pragma unroll
        for (int j = 0; j < 8; ++j)
            #pragma unroll
            for (int q = 0; q < 4; ++q) acc[i][j][q] = 0.f;

    for (int kc = 0; kc < 12; ++kc) {
        __syncthreads();
        // B chunk: 128 c x 16 u32
        #pragma unroll
        for (int p = 0; p < 8; ++p) {
            int i = tid + p * 256;
            int c = i >> 4, kk = i & 15;
            Bch[c * 18 + kk] = g_lwB[c * 192 + kc * 16 + kk];
        }
        // A chunk: convert G floats -> bf16 pairs. blk = kc/4: 0,1 -> hi; 2 -> lo
        {
            int lo = (kc >> 2) == 2;
            int kbase = (kc & 3) * 32;
            #pragma unroll
            for (int p = 0; p < 8; ++p) {
                int i = tid + p * 256;
                int r = i >> 4, kk = i & 15;
                long row = r0 + r; if (row >= NCOL) row = NCOL - 1;
                float2 v = *(const float2*)&g_buf0[row * 128 + kbase + kk * 2];
                __nv_bfloat16 b0, b1;
                if (!lo) {
                    b0 = __float2bfloat16(v.x);
                    b1 = __float2bfloat16(v.y);
                } else {
                    __nv_bfloat16 h0 = __float2bfloat16(v.x);
                    __nv_bfloat16 h1 = __float2bfloat16(v.y);
                    b0 = __float2bfloat16(v.x - __bfloat162float(h0));
                    b1 = __float2bfloat16(v.y - __bfloat162float(h1));
                }
                Ach[r * 18 + kk] = pkbf(b0, b1);
            }
        }
        __syncthreads();
        #pragma unroll
        for (int s = 0; s < 2; ++s) {
            unsigned bf0[8], bf1[8];
            #pragma unroll
            for (int j = 0; j < 8; ++j) {
                int c = nw * 64 + j * 8 + g;
                bf0[j] = Bch[c * 18 + s * 8 + tg];
                bf1[j] = Bch[c * 18 + s * 8 + tg + 4];
            }
            #pragma unroll
            for (int i = 0; i < 2; ++i) {
                int rr = mw * 32 + i * 16 + g;
                int base0 = rr * 18 + s * 8 + tg;
                int base1 = (rr + 8) * 18 + s * 8 + tg;
                unsigned a0 = Ach[base0], a1 = Ach[base1];
                unsigned a2 = Ach[base0 + 4], a3 = Ach[base1 + 4];
                #pragma unroll
                for (int j = 0; j < 8; ++j)
                    mma16816(acc[i][j][0], acc[i][j][1], acc[i][j][2], acc[i][j][3],
                             a0, a1, a2, a3, bf0[j], bf1[j]);
            }
        }
    }
    __syncthreads();

    // Epilogue: bias, store, stats
    int b0idx = (int)(r0 / 62500);
    float s0 = 0.f, q0 = 0.f, s1 = 0.f, q1 = 0.f;
    #pragma unroll
    for (int i = 0; i < 2; ++i) {
        long ra = r0 + mw * 32 + i * 16 + g;
        long rb = ra + 8;
        #pragma unroll
        for (int j = 0; j < 8; ++j) {
            int c = nw * 64 + j * 8 + tg * 2;
            float bv0 = sbias[c], bv1 = sbias[c + 1];
            if (ra < NCOL) {
                float v0 = acc[i][j][0] + bv0;
                float v1 = acc[i][j][1] + bv1;
                *(float2*)&g_buf1[ra * 128 + c] = make_float2(v0, v1);
                float rs = v0 + v1, rq = v0 * v0 + v1 * v1;
                if ((int)(ra / 62500) == b0idx) { s0 += rs; q0 += rq; }
                else                            { s1 += rs; q1 += rq; }
            }
            if (rb < NCOL) {
                float v2 = acc[i][j][2] + bv0;
                float v3 = acc[i][j][3] + bv1;
                *(float2*)&g_buf1[rb * 128 + c] = make_float2(v2, v3);
                float rs = v2 + v3, rq = v2 * v2 + v3 * v3;
                if ((int)(rb / 62500) == b0idx) { s0 += rs; q0 += rq; }
                else                            { s1 += rs; q1 += rq; }
            }
        }
    }
    #pragma unroll
    for (int off = 16; off; off >>= 1) {
        s0 += __shfl_down_sync(0xffffffffu, s0, off);
        q0 += __shfl_down_sync(0xffffffffu, q0, off);
        s1 += __shfl_down_sync(0xffffffffu, s1, off);
        q1 += __shfl_down_sync(0xffffffffu, q1, off);
    }
    if (lane == 0) { red[w][0] = s0; red[w][1] = q0; red[w][2] = s1; red[w][3] = q1; }
    __syncthreads();
    if (tid == 0) {
        float ts0 = 0.f, tq0 = 0.f, ts1 = 0.f, tq1 = 0.f;
        #pragma unroll
        for (int j = 0; j < 8; ++j) {
            ts0 += red[j][0]; tq0 += red[j][1];
            ts1 += red[j][2]; tq1 += red[j][3];
        }
        atomicAdd(&g_stats[2 * b0idx],     (double)ts0);
        atomicAdd(&g_stats[2 * b0idx + 1], (double)tq0);
        if (b0idx < 3) {
            atomicAdd(&g_stats[2 * b0idx + 2], (double)ts1);
            atomicAdd(&g_stats[2 * b0idx + 3], (double)tq1);
        }
    }
}

// ---------------------------------------------------------------------------
__global__ void zero_stats() {
    if (threadIdx.x < 8) g_stats[threadIdx.x] = 0.0;
}

__global__ void finalize_stats() {
    int b = threadIdx.x;
    if (b < 4) {
        double mu  = g_stats[2 * b] / (double)PERB;
        double var = g_stats[2 * b + 1] / (double)PERB - mu * mu;
        g_mu[b]  = (float)mu;
        g_inv[b] = (float)(1.0 / sqrt(var + 1e-8));
    }
}

__global__ void trans_norm_intra(const float* __restrict__ gg, const float* __restrict__ gb,
                                 const float* __restrict__ x, float* __restrict__ out) {
    __shared__ float tile[32][33];
    int bn = blockIdx.y;
    int b = bn >> 7, n = bn & 127;
    int tk = blockIdx.x & 7, ts = blockIdx.x >> 3;
    int s = ts * 32 + threadIdx.y;
    int k = tk * 32 + threadIdx.x;
    if (s < 250 && k < 250)
        tile[threadIdx.y][threadIdx.x] =
            g_buf1[((long)(b * 250 + s)) * 32000 + n * 250 + k];
    __syncthreads();
    int k2 = tk * 32 + threadIdx.y;
    int s2 = ts * 32 + threadIdx.x;
    if (k2 < 250 && s2 < 250) {
        float mu = g_mu[b], inv = g_inv[b];
        long oi = (((long)(b * 128 + n)) * 250 + k2) * 250 + s2;
        float val = (tile[threadIdx.x][threadIdx.y] - mu) * inv * gg[n] + gb[n] + x[oi];
        out[oi] = val;
        g_buf0[(((long)(b * 250 + k2)) * 128 + n) * 250 + s2] = val;
    }
}

__global__ void norm_final(const float* __restrict__ gg, const float* __restrict__ gb,
                           float* __restrict__ out) {
    int i = blockIdx.x * 256 + threadIdx.x;
    int s = i % 250;
    int t = i / 250;
    int k = t % 250; t /= 250;
    int n = t & 127;
    int b = t >> 7;
    float mu = g_mu[b], inv = g_inv[b];
    float v = g_buf1[((long)(b * 250 + k)) * 32000 + n * 250 + s];
    out[i] = (v - mu) * inv * gg[n] + gb[n] + out[i];
}

// ---------------------------------------------------------------------------
extern "C" void kernel_launch(void* const* d_in, const int* in_sizes, int n_in,
                              void* d_out, int out_size) {
    const float* x = (const float*)d_in[0];
    const float* ip[12];
    const float* pp[12];
    for (int j = 0; j < 12; ++j) ip[j] = (const float*)d_in[1 + j];
    for (int j = 0; j < 12; ++j) pp[j] = (const float*)d_in[13 + j];
    float* out = (float*)d_out;

    const int EB = TOT / 256;
    const int SMEM_MMA = 103424;
    cudaFuncSetAttribute(gemm_ow_mma, cudaFuncAttributeMaxDynamicSharedMemorySize, SMEM_MMA);
    const int GOW = (NCOL + 63) / 64;   // 3907

    // ---- intra path ----
    pack_intra<<<dim3(64, 512), dim3(32, 32)>>>(x);
    kern_compute<<<NC, 256>>>(ip[0], ip[1], ip[2], ip[3], ip[4]);
    conv_gemm<<<dim3(16, 128), 256>>>(ip[5]);
    conv_ow_bf16<<<64, 256>>>(ip[6]);
    conv_lw_bf16<<<32, 256>>>(ip[8]);
    gemm_ow_mma<<<GOW, 256, SMEM_MMA>>>(ip[7]);
    zero_stats<<<1, 32>>>();
    gemm_lw_mma<<<1954, 256>>>(ip[9]);
    finalize_stats<<<1, 32>>>();
    trans_norm_intra<<<dim3(64, 512), dim3(32, 32)>>>(ip[10], ip[11], x, out);

    // ---- inter path ----
    kern_compute<<<NC, 256>>>(pp[0], pp[1], pp[2], pp[3], pp[4]);
    conv_gemm<<<dim3(16, 128), 256>>>(pp[5]);
    conv_ow_bf16<<<64, 256>>>(pp[6]);
    conv_lw_bf16<<<32, 256>>>(pp[8]);
    gemm_ow_mma<<<GOW, 256, SMEM_MMA>>>(pp[7]);
    zero_stats<<<1, 32>>>();
    gemm_lw_mma<<<1954, 256>>>(pp[9]);
    finalize_stats<<<1, 32>>>();
    norm_final<<<EB, 256>>>(pp[10], pp[11], out);
}